// round 8
// baseline (speedup 1.0000x reference)
#include <cuda_runtime.h>
#include <cuda_fp16.h>
#include <cstdint>
#include <cstddef>

#define N_USERS 50000
#define N_PRODS 50000
#define NN      100000
#define NE      600000
#define HDIM    128
#define ODIM    16
#define NBLK1   98        // ceil(NN/1024)

// Scratch (__device__ globals: allocation-free rule)
__device__ float    g_x[(size_t)NN * HDIM];
__device__ float    g_y[(size_t)NN * HDIM];
__device__ float    g_dinv[NN];
__device__ int      g_deg[NN];
__device__ int      g_rowstart[NN + 1];
__device__ int      g_cursor[NN];
__device__ int      g_esrc[NE];
__device__ int      g_blksum[NBLK1];
__device__ int      g_is64;
__device__ uint32_t g_wfrag[5 * 8192];    // f16 B-fragments (packed half2 words)

// ---------------------------------------------------------------------------
// fp16 helpers (sm_80-class PTX only)
// ---------------------------------------------------------------------------
__device__ __forceinline__ uint32_t packh2(float lo, float hi) {
    __half2 h = __floats2half2_rn(lo, hi);   // x=lo -> low bits
    return *reinterpret_cast<uint32_t*>(&h);
}
__device__ __forceinline__ void mma_f16(float* c, const uint32_t* a, const uint32_t* b) {
    asm volatile(
        "mma.sync.aligned.m16n8k16.row.col.f32.f16.f16.f32 "
        "{%0,%1,%2,%3}, {%4,%5,%6,%7}, {%8,%9}, {%0,%1,%2,%3};"
        : "+f"(c[0]), "+f"(c[1]), "+f"(c[2]), "+f"(c[3])
        : "r"(a[0]), "r"(a[1]), "r"(a[2]), "r"(a[3]), "r"(b[0]), "r"(b[1]));
}

// ---------------------------------------------------------------------------
// Precompute f16 B fragments for all 5 weights.
// m16n8k16 B map (16x8 tile): reg b0 = {B[tg*2][n'], B[tg*2+1][n']} (lo,hi),
// b1 = rows +8. word offset in tile = lane*2 + reg, lane = n'*4 + tg.
// Tile (k16, nt) at (k16*16 + nt)*64 words. Per-weight stride 8192 words.
// ---------------------------------------------------------------------------
__global__ __launch_bounds__(256) void k_wfrag(
    const float* __restrict__ Wu, const float* __restrict__ Wp,
    const float* __restrict__ W1, const float* __restrict__ W2,
    const float* __restrict__ W3)
{
    const int slot = blockIdx.x >> 3;
    const int chunk = blockIdx.x & 7;        // 1024 words per chunk = one k16 row
    const float* W;
    int Kdim;
    switch (slot) {
        case 0: W = Wu; Kdim = 64;  break;
        case 1: W = Wp; Kdim = 100; break;
        case 2: W = W1; Kdim = 128; break;
        case 3: W = W2; Kdim = 128; break;
        default: W = W3; Kdim = 128; break;
    }
    const int k16cnt = (Kdim + 15) >> 4;
    if (chunk >= k16cnt) return;
    uint32_t* dst = g_wfrag + slot * 8192;
#pragma unroll
    for (int i = 0; i < 4; i++) {
        int w = chunk * 1024 + threadIdx.x + i * 256;
        int nt   = (w >> 6) & 15;
        int widx = w & 63;
        int reg  = widx & 1;
        int lane = widx >> 1;
        int n  = nt * 8 + (lane >> 2);
        int tg = lane & 3;
        int k  = chunk * 16 + tg * 2 + reg * 8;
        float lo = (k     < Kdim) ? W[(size_t)k * HDIM + n] : 0.f;
        float hi = (k + 1 < Kdim) ? W[(size_t)(k + 1) * HDIM + n] : 0.f;
        dst[w] = packh2(lo, hi);
    }
}

// ---------------------------------------------------------------------------
// f16 mma.sync GEMM, NO SMEM: 256 thr, 128x128 CTA tile, warp tile 32x64.
// A: LDG.64 float2 pairs from row-major f32 A (L1-resident), cvt to f16x2.
// B: coalesced LDG.64 from precomputed g_wfrag fragments (L2-resident).
// m16n8k16 A map: a0={A[g][c0],A[g][c0+1]}, a1=rows+8, a2/a3=cols+8;
//                 c0 = k16*16 + tg*2.
// mode=0: out = acc + bias. mode=1: out = acc (-> g_y).
// CGUARD: column guards for Kdim not multiple of 16.
// ---------------------------------------------------------------------------
template<bool CGUARD>
__global__ __launch_bounds__(256, 2) void k_gemm_h(
    const float* __restrict__ A, int lda, int M, int Kdim,
    const uint32_t* __restrict__ Bfrag, const float* __restrict__ bias,
    float* __restrict__ out, int mode)
{
    const int tid = threadIdx.x;
    const int wid = tid >> 5;
    const int lane = tid & 31;
    const int m0 = blockIdx.x * 128;
    const int wm = wid & 3;        // m-block of 32
    const int wn = wid >> 2;       // n-block of 64 (0..1)
    const int g = lane >> 2, tg = lane & 3;

    const int k16cnt = (Kdim + 15) >> 4;

    // Per-warp A row pointers (rows rbase + {0,8,16,24}); clamp invalid to row 0
    const int rbase = m0 + wm * 32 + g;
    int rows[4];
    rows[0] = rbase;      rows[1] = rbase + 8;
    rows[2] = rbase + 16; rows[3] = rbase + 24;
    const float* Ap[4];
#pragma unroll
    for (int i = 0; i < 4; i++)
        Ap[i] = A + (size_t)(rows[i] < M ? rows[i] : 0) * lda;

    const uint2* Bw = (const uint2*)(Bfrag + (wn * 8) * 64) + lane;

    float acc[2][8][4];
#pragma unroll
    for (int mt = 0; mt < 2; mt++)
#pragma unroll
        for (int nt = 0; nt < 8; nt++)
#pragma unroll
            for (int j = 0; j < 4; j++) acc[mt][nt][j] = 0.f;

#pragma unroll 4
    for (int k16 = 0; k16 < k16cnt; k16++) {
        const int c0 = k16 * 16 + tg * 2;

        uint32_t a[2][4];
#pragma unroll
        for (int mt = 0; mt < 2; mt++) {
            const float* p0 = Ap[2 * mt + 0];
            const float* p1 = Ap[2 * mt + 1];
            float2 v0, v1, v2, v3;
            if (!CGUARD) {
                v0 = *(const float2*)(p0 + c0);
                v1 = *(const float2*)(p1 + c0);
                v2 = *(const float2*)(p0 + c0 + 8);
                v3 = *(const float2*)(p1 + c0 + 8);
            } else {
                v0 = v1 = v2 = v3 = make_float2(0.f, 0.f);
                if (c0 + 1 < Kdim) {
                    v0 = *(const float2*)(p0 + c0);
                    v1 = *(const float2*)(p1 + c0);
                } else if (c0 < Kdim) {
                    v0.x = p0[c0]; v1.x = p1[c0];
                }
                if (c0 + 9 < Kdim) {
                    v2 = *(const float2*)(p0 + c0 + 8);
                    v3 = *(const float2*)(p1 + c0 + 8);
                } else if (c0 + 8 < Kdim) {
                    v2.x = p0[c0 + 8]; v3.x = p1[c0 + 8];
                }
            }
            a[mt][0] = packh2(v0.x, v0.y);
            a[mt][1] = packh2(v1.x, v1.y);
            a[mt][2] = packh2(v2.x, v2.y);
            a[mt][3] = packh2(v3.x, v3.y);
        }
        uint32_t b[8][2];
#pragma unroll
        for (int nt = 0; nt < 8; nt++) {
            uint2 t = Bw[(k16 * 16 + nt) * 32];    // 64 words = 32 uint2
            b[nt][0] = t.x; b[nt][1] = t.y;
        }
#pragma unroll
        for (int mt = 0; mt < 2; mt++)
#pragma unroll
            for (int nt = 0; nt < 8; nt++)
                mma_f16(acc[mt][nt], a[mt], b[nt]);
    }

    // ---- epilogue ----
#pragma unroll
    for (int mt = 0; mt < 2; mt++) {
        int r0 = rows[2 * mt + 0];
        int r1 = rows[2 * mt + 1];
#pragma unroll
        for (int nt = 0; nt < 8; nt++) {
            int col = wn * 64 + nt * 8 + tg * 2;
            float2 v0 = make_float2(acc[mt][nt][0], acc[mt][nt][1]);
            float2 v1 = make_float2(acc[mt][nt][2], acc[mt][nt][3]);
            if (mode == 0) {
                float2 bb = *(const float2*)&bias[col];
                v0.x += bb.x; v0.y += bb.y;
                v1.x += bb.x; v1.y += bb.y;
            }
            if (r0 < M) *(float2*)&out[(size_t)r0 * HDIM + col] = v0;
            if (r1 < M) *(float2*)&out[(size_t)r1 * HDIM + col] = v1;
        }
    }
}

// ---------------------------------------------------------------------------
// Edge dtype detect + CSR build
// ---------------------------------------------------------------------------
__global__ void k_detect(const void* __restrict__ edges) {
    if (threadIdx.x == 0 && blockIdx.x == 0) {
        const unsigned int* w = (const unsigned int*)edges;
        int is64 = 1;
        for (int i = 0; i < 64; i++)
            if (w[2 * i + 1] != 0u) { is64 = 0; break; }
        g_is64 = is64;
    }
}
__global__ void k_zero() {
    int i = blockIdx.x * blockDim.x + threadIdx.x;
    if (i < NN) g_deg[i] = 0;
}
__device__ __forceinline__ void load_edge(const void* edges, int i, int& s, int& d) {
    if (g_is64) {
        const long long* e = (const long long*)edges;
        s = (int)e[i]; d = (int)e[NE + i];
    } else {
        const int* e = (const int*)edges;
        s = e[i]; d = e[NE + i];
    }
}
__global__ void k_hist(const void* __restrict__ edges) {
    int i = blockIdx.x * blockDim.x + threadIdx.x;
    if (i >= NE) return;
    int s, d; load_edge(edges, i, s, d);
    atomicAdd(&g_deg[d], 1);
}
__global__ __launch_bounds__(256) void k_scan1() {
    __shared__ int wsum[8], wbase[8];
    int b = blockIdx.x, tid = threadIdx.x;
    int base = b * 1024 + tid * 4;
    int v0 = 0, v1 = 0, v2 = 0, v3 = 0;
    if (base + 3 < NN) {
        int4 t = *(const int4*)&g_deg[base];
        v0 = t.x; v1 = t.y; v2 = t.z; v3 = t.w;
    } else {
        if (base + 0 < NN) v0 = g_deg[base + 0];
        if (base + 1 < NN) v1 = g_deg[base + 1];
        if (base + 2 < NN) v2 = g_deg[base + 2];
        if (base + 3 < NN) v3 = g_deg[base + 3];
    }
    int s = v0 + v1 + v2 + v3;
    int lane = tid & 31, w = tid >> 5;
    int x = s;
#pragma unroll
    for (int off = 1; off < 32; off <<= 1) {
        int t = __shfl_up_sync(0xffffffffu, x, off);
        if (lane >= off) x += t;
    }
    if (lane == 31) wsum[w] = x;
    __syncthreads();
    if (tid == 0) {
        int run = 0;
#pragma unroll
        for (int i = 0; i < 8; i++) { wbase[i] = run; run += wsum[i]; }
        g_blksum[b] = run;
    }
    __syncthreads();
    int ex = wbase[w] + x - s;
    if (base + 0 < NN) g_rowstart[base + 0] = ex;
    if (base + 1 < NN) g_rowstart[base + 1] = ex + v0;
    if (base + 2 < NN) g_rowstart[base + 2] = ex + v0 + v1;
    if (base + 3 < NN) g_rowstart[base + 3] = ex + v0 + v1 + v2;
}
__global__ __launch_bounds__(128) void k_scan2() {
    __shared__ int sh[NBLK1];
    int tid = threadIdx.x;
    if (tid < NBLK1) sh[tid] = g_blksum[tid];
    __syncthreads();
    if (tid == 0) {
        int run = 0;
        for (int i = 0; i < NBLK1; i++) { int t = sh[i]; sh[i] = run; run += t; }
    }
    __syncthreads();
    if (tid < NBLK1) g_blksum[tid] = sh[tid];
}
__global__ void k_scan3() {
    int i = blockIdx.x * blockDim.x + threadIdx.x;
    if (i >= NN) return;
    int rs = g_rowstart[i] + g_blksum[i >> 10];
    g_rowstart[i] = rs;
    g_cursor[i] = rs;
    g_dinv[i] = rsqrtf((float)g_deg[i] + 1.0f);
    if (i == 0) g_rowstart[NN] = NE;
}
__global__ void k_fill(const void* __restrict__ edges) {
    int i = blockIdx.x * blockDim.x + threadIdx.x;
    if (i >= NE) return;
    int s, d; load_edge(edges, i, s, d);
    int pos = atomicAdd(&g_cursor[d], 1);
    g_esrc[pos] = s;
}

// ---------------------------------------------------------------------------
// CSR gather + fused ReLU
// ---------------------------------------------------------------------------
__global__ __launch_bounds__(256) void k_gather(const float* __restrict__ bias) {
    int gt = blockIdx.x * blockDim.x + threadIdx.x;
    int node = gt >> 5;
    int lane = gt & 31;
    if (node >= NN) return;

    float dd = g_dinv[node];
    float4 acc = *(const float4*)&g_y[(size_t)node * HDIM + lane * 4];
    acc.x *= dd; acc.y *= dd; acc.z *= dd; acc.w *= dd;

    int e = g_rowstart[node];
    const int end = g_rowstart[node + 1];
    for (; e + 4 <= end; e += 4) {
        int s0 = g_esrc[e], s1 = g_esrc[e + 1], s2 = g_esrc[e + 2], s3 = g_esrc[e + 3];
        float n0 = g_dinv[s0], n1 = g_dinv[s1], n2 = g_dinv[s2], n3 = g_dinv[s3];
        float4 a = *(const float4*)&g_y[(size_t)s0 * HDIM + lane * 4];
        float4 b = *(const float4*)&g_y[(size_t)s1 * HDIM + lane * 4];
        float4 c = *(const float4*)&g_y[(size_t)s2 * HDIM + lane * 4];
        float4 d = *(const float4*)&g_y[(size_t)s3 * HDIM + lane * 4];
        acc.x += a.x * n0 + b.x * n1 + c.x * n2 + d.x * n3;
        acc.y += a.y * n0 + b.y * n1 + c.y * n2 + d.y * n3;
        acc.z += a.z * n0 + b.z * n1 + c.z * n2 + d.z * n3;
        acc.w += a.w * n0 + b.w * n1 + c.w * n2 + d.w * n3;
    }
    for (; e < end; e++) {
        int s = g_esrc[e];
        float ns = g_dinv[s];
        float4 a = *(const float4*)&g_y[(size_t)s * HDIM + lane * 4];
        acc.x += a.x * ns; acc.y += a.y * ns; acc.z += a.z * ns; acc.w += a.w * ns;
    }
    float4 bb = *(const float4*)&bias[lane * 4];
    float4 o;
    o.x = fmaxf(acc.x * dd + bb.x, 0.f);
    o.y = fmaxf(acc.y * dd + bb.y, 0.f);
    o.z = fmaxf(acc.z * dd + bb.z, 0.f);
    o.w = fmaxf(acc.w * dd + bb.w, 0.f);
    *(float4*)&g_x[(size_t)node * HDIM + lane * 4] = o;
}

// ---------------------------------------------------------------------------
// Output GEMM: out[NN,16] = g_x @ Wo + bo   (g_x already relu'd)
// ---------------------------------------------------------------------------
__global__ __launch_bounds__(256) void k_out(
    const float* __restrict__ Wo, const float* __restrict__ bo,
    float* __restrict__ out)
{
    __shared__ float sX[64][HDIM];
    __shared__ float sW[HDIM][ODIM];
    const int tid = threadIdx.x;
    const int m0 = blockIdx.x * 64;

#pragma unroll
    for (int it = 0; it < 8; it++) {
        int idx = tid + it * 256;
        int r = idx >> 5;
        int c4 = (idx & 31) * 4;
        int gm = m0 + r;
        float4 v = make_float4(0.f, 0.f, 0.f, 0.f);
        if (gm < NN) v = *(const float4*)&g_x[(size_t)gm * HDIM + c4];
        *(float4*)&sX[r][c4] = v;
    }
#pragma unroll
    for (int it = 0; it < 8; it++) {
        int idx = tid + it * 256;
        ((float*)sW)[idx] = Wo[idx];
    }
    __syncthreads();

    const int col = tid & 15;
    const int r0 = (tid >> 4) * 4;
    float acc[4] = {0.f, 0.f, 0.f, 0.f};
#pragma unroll 4
    for (int k = 0; k < HDIM; k++) {
        float w = sW[k][col];
        acc[0] += sX[r0 + 0][k] * w;
        acc[1] += sX[r0 + 1][k] * w;
        acc[2] += sX[r0 + 2][k] * w;
        acc[3] += sX[r0 + 3][k] * w;
    }
    float bb = bo[col];
#pragma unroll
    for (int i = 0; i < 4; i++) {
        int gm = m0 + r0 + i;
        if (gm < NN) out[(size_t)gm * ODIM + col] = acc[i] + bb;
    }
}

// ---------------------------------------------------------------------------
extern "C" void kernel_launch(void* const* d_in, const int* in_sizes, int n_in,
                              void* d_out, int out_size) {
    const float* user = (const float*)d_in[0];
    const float* prod = (const float*)d_in[1];
    const void*  edges = d_in[2];
    const float* Wu = (const float*)d_in[3];
    const float* bu = (const float*)d_in[4];
    const float* Wp = (const float*)d_in[5];
    const float* bp = (const float*)d_in[6];
    const float* W1 = (const float*)d_in[7];
    const float* b1 = (const float*)d_in[8];
    const float* W2 = (const float*)d_in[9];
    const float* b2 = (const float*)d_in[10];
    const float* W3 = (const float*)d_in[11];
    const float* b3 = (const float*)d_in[12];
    const float* Wo = (const float*)d_in[13];
    const float* bo = (const float*)d_in[14];
    float* out = (float*)d_out;

    float *px = nullptr, *py = nullptr;
    uint32_t* pw = nullptr;
    cudaGetSymbolAddress((void**)&px, g_x);
    cudaGetSymbolAddress((void**)&py, g_y);
    cudaGetSymbolAddress((void**)&pw, g_wfrag);

    // 1: f16 B fragments for all 5 weights
    k_wfrag<<<40, 256>>>(Wu, Wp, W1, W2, W3);

    // 2-3: input transforms -> g_x (bias added; no relu: conv1 input)
    k_gemm_h<false><<<(N_USERS + 127) / 128, 256>>>(
        user, 64, N_USERS, 64, pw + 0 * 8192, bu, px, 0);
    k_gemm_h<true><<<(N_PRODS + 127) / 128, 256>>>(
        prod, 100, N_PRODS, 100, pw + 1 * 8192, bp,
        px + (size_t)N_USERS * HDIM, 0);

    // 4: layer-1 GEMM (profiled slot #4)
    k_gemm_h<false><<<(NN + 127) / 128, 256>>>(
        px, 128, NN, 128, pw + 2 * 8192, nullptr, py, 1);

    // 5-11: CSR build (independent of GEMMs above)
    k_detect<<<1, 32>>>(edges);
    k_zero<<<(NN + 255) / 256, 256>>>();
    k_hist<<<(NE + 255) / 256, 256>>>(edges);
    k_scan1<<<NBLK1, 256>>>();
    k_scan2<<<1, 128>>>();
    k_scan3<<<(NN + 255) / 256, 256>>>();
    k_fill<<<(NE + 255) / 256, 256>>>(edges);

    // layer 1 gather (+relu)
    k_gather<<<(NN * 32 + 255) / 256, 256>>>(b1);

    // layers 2,3
    k_gemm_h<false><<<(NN + 127) / 128, 256>>>(
        px, 128, NN, 128, pw + 3 * 8192, nullptr, py, 1);
    k_gather<<<(NN * 32 + 255) / 256, 256>>>(b2);

    k_gemm_h<false><<<(NN + 127) / 128, 256>>>(
        px, 128, NN, 128, pw + 4 * 8192, nullptr, py, 1);
    k_gather<<<(NN * 32 + 255) / 256, 256>>>(b3);

    k_out<<<(NN + 63) / 64, 256>>>(Wo, bo, out);
}

// round 9
// speedup vs baseline: 1.3274x; 1.3274x over previous
#include <cuda_runtime.h>
#include <cstdint>
#include <cstddef>

#define N_USERS 50000
#define N_PRODS 50000
#define NN      100000
#define NE      600000
#define HDIM    128
#define ODIM    16
#define NBLK1   98        // ceil(NN/1024)

// Scratch (__device__ globals: allocation-free rule)
__device__ float    g_x[(size_t)NN * HDIM];
__device__ float    g_y[(size_t)NN * HDIM];
__device__ float    g_dinv[NN];
__device__ int      g_deg[NN];
__device__ int      g_rowstart[NN + 1];
__device__ int      g_cursor[NN];
__device__ int      g_esrc[NE];
__device__ int      g_blksum[NBLK1];
__device__ int      g_is64;
__device__ uint32_t g_wfrag[5 * 16384];   // tf32 B-fragments for the 5 weights

// ---------------------------------------------------------------------------
// tf32 helpers (sm_80-class PTX only)
// ---------------------------------------------------------------------------
__device__ __forceinline__ uint32_t f2tf32(float f) {
    uint32_t u;
    asm("cvt.rna.tf32.f32 %0, %1;" : "=r"(u) : "f"(f));
    return u;
}
__device__ __forceinline__ void mma_tf32(float* c, const uint32_t* a, const uint32_t* b) {
    asm volatile(
        "mma.sync.aligned.m16n8k8.row.col.f32.tf32.tf32.f32 "
        "{%0,%1,%2,%3}, {%4,%5,%6,%7}, {%8,%9}, {%0,%1,%2,%3};"
        : "+f"(c[0]), "+f"(c[1]), "+f"(c[2]), "+f"(c[3])
        : "r"(a[0]), "r"(a[1]), "r"(a[2]), "r"(a[3]), "r"(b[0]), "r"(b[1]));
}
// B fragment word offset for (k, n): lane=(n&7)*4+(k&3), reg=(k>>2)&1;
// tile (k8, nt) at (k8*16+nt)*64 words.
__device__ __forceinline__ uint32_t bfrag_off(int k, int n) {
    return (uint32_t)(((k >> 3) * 16 + (n >> 3)) * 64
                    + ((n & 7) * 4 + (k & 3)) * 2 + ((k >> 2) & 1));
}

// ---------------------------------------------------------------------------
// Precompute tf32 B fragments for all 5 weights.
// ---------------------------------------------------------------------------
__global__ __launch_bounds__(256) void k_wfrag(
    const float* __restrict__ Wu, const float* __restrict__ Wp,
    const float* __restrict__ W1, const float* __restrict__ W2,
    const float* __restrict__ W3)
{
    const int slot = blockIdx.x >> 4;
    const int k0 = (blockIdx.x & 15) * 8;
    const float* W;
    int Kdim;
    switch (slot) {
        case 0: W = Wu; Kdim = 64;  break;
        case 1: W = Wp; Kdim = 100; break;
        case 2: W = W1; Kdim = 128; break;
        case 3: W = W2; Kdim = 128; break;
        default: W = W3; Kdim = 128; break;
    }
    const int Kpad = (Kdim + 7) & ~7;
    if (k0 >= Kpad) return;
    uint32_t* dst = g_wfrag + slot * 16384;
#pragma unroll
    for (int i = 0; i < 4; i++) {
        int idx = threadIdx.x + i * 256;        // 0..1023
        int k = k0 + (idx >> 7), n = idx & 127;
        if (k >= Kpad) continue;
        float v = (k < Kdim) ? W[(size_t)k * HDIM + n] : 0.f;
        dst[bfrag_off(k, n)] = f2tf32(v);
    }
}

// ---------------------------------------------------------------------------
// tf32 mma.sync GEMM: 256 thr, 128x128 CTA tile, warp tile 32x64.
// A: staged to SMEM row-major tf32, row stride KPAD+4 words (stride%8==4 =>
//    all fragment LDS.32 reads are 32-bank conflict-free), zero-padded, so
//    mainloop has NO guards. B: coalesced LDG.64 from g_wfrag (L2-resident).
// mode=0: out = acc + bias. mode=1: out = acc (-> g_y).
// ---------------------------------------------------------------------------
template<int KDIM, int KPAD>
__global__ __launch_bounds__(256, 2) void k_gemm(
    const float* __restrict__ A, int M,
    const uint32_t* __restrict__ Bfrag, const float* __restrict__ bias,
    float* __restrict__ out, int mode)
{
    constexpr int STRIDE = KPAD + 4;           // words; %8 == 4 -> conflict-free
    constexpr int K8 = KPAD / 8;
    extern __shared__ uint32_t sA[];           // 128 * STRIDE words

    const int tid = threadIdx.x;
    const int wid = tid >> 5;
    const int lane = tid & 31;
    const int m0 = blockIdx.x * 128;
    const int wm = wid & 3;        // m-block of 32
    const int wn = wid >> 2;       // n-block of 64 (0..1)
    const int g = lane >> 2, tg = lane & 3;

    // ---- stage A: 128 rows x KPAD cols (tf32), coalesced, zero-padded ----
    constexpr int NC4 = KPAD / 4;              // float4 per row
#pragma unroll
    for (int it = 0; it < 128 * NC4 / 256; it++) {
        int idx4 = tid + it * 256;
        int r = idx4 / NC4;
        int c4 = (idx4 - r * NC4) * 4;
        int gm = m0 + r;
        float4 v = make_float4(0.f, 0.f, 0.f, 0.f);
        if (gm < M && c4 < KDIM)
            v = *(const float4*)&A[(size_t)gm * KDIM + c4];
        uint32_t* p = sA + r * STRIDE + c4;
        p[0] = f2tf32(v.x); p[1] = f2tf32(v.y);
        p[2] = f2tf32(v.z); p[3] = f2tf32(v.w);
    }
    __syncthreads();

    float acc[2][8][4];
#pragma unroll
    for (int mt = 0; mt < 2; mt++)
#pragma unroll
        for (int nt = 0; nt < 8; nt++)
#pragma unroll
            for (int j = 0; j < 4; j++) acc[mt][nt][j] = 0.f;

    const uint32_t* sAr = sA + (wm * 32 + g) * STRIDE + tg;   // row r0, col tg
    const uint2* Bw = (const uint2*)(Bfrag + (wn * 8) * 64) + lane;

#pragma unroll
    for (int k8 = 0; k8 < K8; k8++) {
        const int c0 = k8 * 8;
        uint32_t a[2][4];
#pragma unroll
        for (int mt = 0; mt < 2; mt++) {
            const uint32_t* p = sAr + mt * 16 * STRIDE;
            a[mt][0] = p[c0];
            a[mt][1] = p[8 * STRIDE + c0];
            a[mt][2] = p[c0 + 4];
            a[mt][3] = p[8 * STRIDE + c0 + 4];
        }
        uint32_t b[8][2];
#pragma unroll
        for (int nt = 0; nt < 8; nt++) {
            uint2 t = Bw[(k8 * 16 + nt) * 32];   // 64 words = 32 uint2
            b[nt][0] = t.x; b[nt][1] = t.y;
        }
#pragma unroll
        for (int mt = 0; mt < 2; mt++)
#pragma unroll
            for (int nt = 0; nt < 8; nt++)
                mma_tf32(acc[mt][nt], a[mt], b[nt]);
    }

    // ---- epilogue ----
    const int rbase = m0 + wm * 32 + g;
#pragma unroll
    for (int mt = 0; mt < 2; mt++) {
        int r0 = rbase + mt * 16;
        int r1 = r0 + 8;
#pragma unroll
        for (int nt = 0; nt < 8; nt++) {
            int col = wn * 64 + nt * 8 + tg * 2;
            float2 v0 = make_float2(acc[mt][nt][0], acc[mt][nt][1]);
            float2 v1 = make_float2(acc[mt][nt][2], acc[mt][nt][3]);
            if (mode == 0) {
                float2 bb = *(const float2*)&bias[col];
                v0.x += bb.x; v0.y += bb.y;
                v1.x += bb.x; v1.y += bb.y;
            }
            if (r0 < M) *(float2*)&out[(size_t)r0 * HDIM + col] = v0;
            if (r1 < M) *(float2*)&out[(size_t)r1 * HDIM + col] = v1;
        }
    }
}

// ---------------------------------------------------------------------------
// Edge dtype detect + CSR build
// ---------------------------------------------------------------------------
__global__ void k_detect(const void* __restrict__ edges) {
    if (threadIdx.x == 0 && blockIdx.x == 0) {
        const unsigned int* w = (const unsigned int*)edges;
        int is64 = 1;
        for (int i = 0; i < 64; i++)
            if (w[2 * i + 1] != 0u) { is64 = 0; break; }
        g_is64 = is64;
    }
}
__global__ void k_zero() {
    int i = blockIdx.x * blockDim.x + threadIdx.x;
    if (i < NN) g_deg[i] = 0;
}
__device__ __forceinline__ void load_edge(const void* edges, int i, int& s, int& d) {
    if (g_is64) {
        const long long* e = (const long long*)edges;
        s = (int)e[i]; d = (int)e[NE + i];
    } else {
        const int* e = (const int*)edges;
        s = e[i]; d = e[NE + i];
    }
}
__global__ void k_hist(const void* __restrict__ edges) {
    int i = blockIdx.x * blockDim.x + threadIdx.x;
    if (i >= NE) return;
    int s, d; load_edge(edges, i, s, d);
    atomicAdd(&g_deg[d], 1);
}
__global__ __launch_bounds__(256) void k_scan1() {
    __shared__ int wsum[8], wbase[8];
    int b = blockIdx.x, tid = threadIdx.x;
    int base = b * 1024 + tid * 4;
    int v0 = 0, v1 = 0, v2 = 0, v3 = 0;
    if (base + 3 < NN) {
        int4 t = *(const int4*)&g_deg[base];
        v0 = t.x; v1 = t.y; v2 = t.z; v3 = t.w;
    } else {
        if (base + 0 < NN) v0 = g_deg[base + 0];
        if (base + 1 < NN) v1 = g_deg[base + 1];
        if (base + 2 < NN) v2 = g_deg[base + 2];
        if (base + 3 < NN) v3 = g_deg[base + 3];
    }
    int s = v0 + v1 + v2 + v3;
    int lane = tid & 31, w = tid >> 5;
    int x = s;
#pragma unroll
    for (int off = 1; off < 32; off <<= 1) {
        int t = __shfl_up_sync(0xffffffffu, x, off);
        if (lane >= off) x += t;
    }
    if (lane == 31) wsum[w] = x;
    __syncthreads();
    if (tid == 0) {
        int run = 0;
#pragma unroll
        for (int i = 0; i < 8; i++) { wbase[i] = run; run += wsum[i]; }
        g_blksum[b] = run;
    }
    __syncthreads();
    int ex = wbase[w] + x - s;
    if (base + 0 < NN) g_rowstart[base + 0] = ex;
    if (base + 1 < NN) g_rowstart[base + 1] = ex + v0;
    if (base + 2 < NN) g_rowstart[base + 2] = ex + v0 + v1;
    if (base + 3 < NN) g_rowstart[base + 3] = ex + v0 + v1 + v2;
}
__global__ __launch_bounds__(128) void k_scan2() {
    __shared__ int sh[NBLK1];
    int tid = threadIdx.x;
    if (tid < NBLK1) sh[tid] = g_blksum[tid];
    __syncthreads();
    if (tid == 0) {
        int run = 0;
        for (int i = 0; i < NBLK1; i++) { int t = sh[i]; sh[i] = run; run += t; }
    }
    __syncthreads();
    if (tid < NBLK1) g_blksum[tid] = sh[tid];
}
__global__ void k_scan3() {
    int i = blockIdx.x * blockDim.x + threadIdx.x;
    if (i >= NN) return;
    int rs = g_rowstart[i] + g_blksum[i >> 10];
    g_rowstart[i] = rs;
    g_cursor[i] = rs;
    g_dinv[i] = rsqrtf((float)g_deg[i] + 1.0f);
    if (i == 0) g_rowstart[NN] = NE;
}
__global__ void k_fill(const void* __restrict__ edges) {
    int i = blockIdx.x * blockDim.x + threadIdx.x;
    if (i >= NE) return;
    int s, d; load_edge(edges, i, s, d);
    int pos = atomicAdd(&g_cursor[d], 1);
    g_esrc[pos] = s;
}

// ---------------------------------------------------------------------------
// CSR gather + fused ReLU
// ---------------------------------------------------------------------------
__global__ __launch_bounds__(256) void k_gather(const float* __restrict__ bias) {
    int gt = blockIdx.x * blockDim.x + threadIdx.x;
    int node = gt >> 5;
    int lane = gt & 31;
    if (node >= NN) return;

    float dd = g_dinv[node];
    float4 acc = *(const float4*)&g_y[(size_t)node * HDIM + lane * 4];
    acc.x *= dd; acc.y *= dd; acc.z *= dd; acc.w *= dd;

    int e = g_rowstart[node];
    const int end = g_rowstart[node + 1];
    for (; e + 4 <= end; e += 4) {
        int s0 = g_esrc[e], s1 = g_esrc[e + 1], s2 = g_esrc[e + 2], s3 = g_esrc[e + 3];
        float n0 = g_dinv[s0], n1 = g_dinv[s1], n2 = g_dinv[s2], n3 = g_dinv[s3];
        float4 a = *(const float4*)&g_y[(size_t)s0 * HDIM + lane * 4];
        float4 b = *(const float4*)&g_y[(size_t)s1 * HDIM + lane * 4];
        float4 c = *(const float4*)&g_y[(size_t)s2 * HDIM + lane * 4];
        float4 d = *(const float4*)&g_y[(size_t)s3 * HDIM + lane * 4];
        acc.x += a.x * n0 + b.x * n1 + c.x * n2 + d.x * n3;
        acc.y += a.y * n0 + b.y * n1 + c.y * n2 + d.y * n3;
        acc.z += a.z * n0 + b.z * n1 + c.z * n2 + d.z * n3;
        acc.w += a.w * n0 + b.w * n1 + c.w * n2 + d.w * n3;
    }
    for (; e < end; e++) {
        int s = g_esrc[e];
        float ns = g_dinv[s];
        float4 a = *(const float4*)&g_y[(size_t)s * HDIM + lane * 4];
        acc.x += a.x * ns; acc.y += a.y * ns; acc.z += a.z * ns; acc.w += a.w * ns;
    }
    float4 bb = *(const float4*)&bias[lane * 4];
    float4 o;
    o.x = fmaxf(acc.x * dd + bb.x, 0.f);
    o.y = fmaxf(acc.y * dd + bb.y, 0.f);
    o.z = fmaxf(acc.z * dd + bb.z, 0.f);
    o.w = fmaxf(acc.w * dd + bb.w, 0.f);
    *(float4*)&g_x[(size_t)node * HDIM + lane * 4] = o;
}

// ---------------------------------------------------------------------------
// Output GEMM: out[NN,16] = g_x @ Wo + bo   (g_x already relu'd)
// ---------------------------------------------------------------------------
__global__ __launch_bounds__(256) void k_out(
    const float* __restrict__ Wo, const float* __restrict__ bo,
    float* __restrict__ out)
{
    __shared__ float sX[64][HDIM];
    __shared__ float sW[HDIM][ODIM];
    const int tid = threadIdx.x;
    const int m0 = blockIdx.x * 64;

#pragma unroll
    for (int it = 0; it < 8; it++) {
        int idx = tid + it * 256;
        int r = idx >> 5;
        int c4 = (idx & 31) * 4;
        int gm = m0 + r;
        float4 v = make_float4(0.f, 0.f, 0.f, 0.f);
        if (gm < NN) v = *(const float4*)&g_x[(size_t)gm * HDIM + c4];
        *(float4*)&sX[r][c4] = v;
    }
#pragma unroll
    for (int it = 0; it < 8; it++) {
        int idx = tid + it * 256;
        ((float*)sW)[idx] = Wo[idx];
    }
    __syncthreads();

    const int col = tid & 15;
    const int r0 = (tid >> 4) * 4;
    float acc[4] = {0.f, 0.f, 0.f, 0.f};
#pragma unroll 4
    for (int k = 0; k < HDIM; k++) {
        float w = sW[k][col];
        acc[0] += sX[r0 + 0][k] * w;
        acc[1] += sX[r0 + 1][k] * w;
        acc[2] += sX[r0 + 2][k] * w;
        acc[3] += sX[r0 + 3][k] * w;
    }
    float bb = bo[col];
#pragma unroll
    for (int i = 0; i < 4; i++) {
        int gm = m0 + r0 + i;
        if (gm < NN) out[(size_t)gm * ODIM + col] = acc[i] + bb;
    }
}

// ---------------------------------------------------------------------------
extern "C" void kernel_launch(void* const* d_in, const int* in_sizes, int n_in,
                              void* d_out, int out_size) {
    const float* user = (const float*)d_in[0];
    const float* prod = (const float*)d_in[1];
    const void*  edges = d_in[2];
    const float* Wu = (const float*)d_in[3];
    const float* bu = (const float*)d_in[4];
    const float* Wp = (const float*)d_in[5];
    const float* bp = (const float*)d_in[6];
    const float* W1 = (const float*)d_in[7];
    const float* b1 = (const float*)d_in[8];
    const float* W2 = (const float*)d_in[9];
    const float* b2 = (const float*)d_in[10];
    const float* W3 = (const float*)d_in[11];
    const float* b3 = (const float*)d_in[12];
    const float* Wo = (const float*)d_in[13];
    const float* bo = (const float*)d_in[14];
    float* out = (float*)d_out;

    float *px = nullptr, *py = nullptr;
    uint32_t* pw = nullptr;
    cudaGetSymbolAddress((void**)&px, g_x);
    cudaGetSymbolAddress((void**)&py, g_y);
    cudaGetSymbolAddress((void**)&pw, g_wfrag);

    const int smem128 = 128 * (128 + 4) * 4;   // 67584
    const int smem104 = 128 * (104 + 4) * 4;   // 55296
    const int smem64  = 128 * (64 + 4) * 4;    // 34816
    cudaFuncSetAttribute(k_gemm<128, 128>, cudaFuncAttributeMaxDynamicSharedMemorySize, smem128);
    cudaFuncSetAttribute(k_gemm<100, 104>, cudaFuncAttributeMaxDynamicSharedMemorySize, smem104);
    cudaFuncSetAttribute(k_gemm<64, 64>,   cudaFuncAttributeMaxDynamicSharedMemorySize, smem64);

    // 1: tf32 B fragments for all 5 weights
    k_wfrag<<<80, 256>>>(Wu, Wp, W1, W2, W3);

    // 2-3: input transforms -> g_x (bias added; no relu: conv1 input)
    k_gemm<64, 64><<<(N_USERS + 127) / 128, 256, smem64>>>(
        user, N_USERS, pw + 0 * 16384, bu, px, 0);
    k_gemm<100, 104><<<(N_PRODS + 127) / 128, 256, smem104>>>(
        prod, N_PRODS, pw + 1 * 16384, bp, px + (size_t)N_USERS * HDIM, 0);

    // 4: layer-1 GEMM (profiled slot #4)
    k_gemm<128, 128><<<(NN + 127) / 128, 256, smem128>>>(
        px, NN, pw + 2 * 16384, nullptr, py, 1);

    // 5-11: CSR build (independent of GEMMs above)
    k_detect<<<1, 32>>>(edges);
    k_zero<<<(NN + 255) / 256, 256>>>();
    k_hist<<<(NE + 255) / 256, 256>>>(edges);
    k_scan1<<<NBLK1, 256>>>();
    k_scan2<<<1, 128>>>();
    k_scan3<<<(NN + 255) / 256, 256>>>();
    k_fill<<<(NE + 255) / 256, 256>>>(edges);

    // layer 1 gather (+relu)
    k_gather<<<(NN * 32 + 255) / 256, 256>>>(b1);

    // layers 2,3
    k_gemm<128, 128><<<(NN + 127) / 128, 256, smem128>>>(
        px, NN, pw + 3 * 16384, nullptr, py, 1);
    k_gather<<<(NN * 32 + 255) / 256, 256>>>(b2);

    k_gemm<128, 128><<<(NN + 127) / 128, 256, smem128>>>(
        px, NN, pw + 4 * 16384, nullptr, py, 1);
    k_gather<<<(NN * 32 + 255) / 256, 256>>>(b3);

    k_out<<<(NN + 63) / 64, 256>>>(Wo, bo, out);
}

// round 10
// speedup vs baseline: 1.7852x; 1.3449x over previous
#include <cuda_runtime.h>
#include <cuda_fp16.h>
#include <cstdint>
#include <cstddef>

#define N_USERS 50000
#define N_PRODS 50000
#define NN      100000
#define NE      600000
#define HDIM    128
#define ODIM    16
#define NBLK1   98        // ceil(NN/1024)

// Scratch (__device__ globals: allocation-free rule)
__device__ __half   g_x[(size_t)NN * HDIM];
__device__ __half   g_y[(size_t)NN * HDIM];
__device__ float    g_dinv[NN];
__device__ int      g_deg[NN];
__device__ int      g_rowstart[NN + 1];
__device__ int      g_cursor[NN];
__device__ int      g_esrc[NE];
__device__ int      g_blksum[NBLK1];
__device__ int      g_is64;
// [0..16384) Wu tf32, [16384..32768) Wp tf32, [32768..) W1/W2/W3 f16 (8192 each)
__device__ uint32_t g_wfrag[57344];

// ---------------------------------------------------------------------------
// helpers (sm_80-class PTX only)
// ---------------------------------------------------------------------------
__device__ __forceinline__ uint32_t f2tf32(float f) {
    uint32_t u;
    asm("cvt.rna.tf32.f32 %0, %1;" : "=r"(u) : "f"(f));
    return u;
}
__device__ __forceinline__ uint32_t packh2(float lo, float hi) {
    __half2 h = __floats2half2_rn(lo, hi);
    return *reinterpret_cast<uint32_t*>(&h);
}
__device__ __forceinline__ void mma_tf32(float* c, const uint32_t* a, const uint32_t* b) {
    asm volatile(
        "mma.sync.aligned.m16n8k8.row.col.f32.tf32.tf32.f32 "
        "{%0,%1,%2,%3}, {%4,%5,%6,%7}, {%8,%9}, {%0,%1,%2,%3};"
        : "+f"(c[0]), "+f"(c[1]), "+f"(c[2]), "+f"(c[3])
        : "r"(a[0]), "r"(a[1]), "r"(a[2]), "r"(a[3]), "r"(b[0]), "r"(b[1]));
}
__device__ __forceinline__ void mma_f16(float* c, const uint32_t* a, const uint32_t* b) {
    asm volatile(
        "mma.sync.aligned.m16n8k16.row.col.f32.f16.f16.f32 "
        "{%0,%1,%2,%3}, {%4,%5,%6,%7}, {%8,%9}, {%0,%1,%2,%3};"
        : "+f"(c[0]), "+f"(c[1]), "+f"(c[2]), "+f"(c[3])
        : "r"(a[0]), "r"(a[1]), "r"(a[2]), "r"(a[3]), "r"(b[0]), "r"(b[1]));
}
// tf32 m16n8k8 B word offset for (k, n)
__device__ __forceinline__ uint32_t bfrag_off(int k, int n) {
    return (uint32_t)(((k >> 3) * 16 + (n >> 3)) * 64
                    + ((n & 7) * 4 + (k & 3)) * 2 + ((k >> 2) & 1));
}

// ---------------------------------------------------------------------------
// Precompute B fragments: tf32 for Wu/Wp, packed-f16 for W1/W2/W3.
// f16 m16n8k16 B map: word w in tile -> reg=w&1, lane=w>>1, n'=lane>>2,
// tg=lane&3; word = {B[tg*2+reg*8][n'], B[tg*2+1+reg*8][n']}.
// ---------------------------------------------------------------------------
__global__ __launch_bounds__(256) void k_wfrag(
    const float* __restrict__ Wu, const float* __restrict__ Wp,
    const float* __restrict__ W1, const float* __restrict__ W2,
    const float* __restrict__ W3)
{
    const int b = blockIdx.x;
    if (b < 32) {
        const int slot = b >> 4;            // 0=Wu, 1=Wp
        const int k0 = (b & 15) * 8;
        const float* W = slot ? Wp : Wu;
        const int Kdim = slot ? 100 : 64;
        const int Kpad = (Kdim + 7) & ~7;
        if (k0 >= Kpad) return;
        uint32_t* dst = g_wfrag + slot * 16384;
#pragma unroll
        for (int i = 0; i < 4; i++) {
            int idx = threadIdx.x + i * 256;
            int k = k0 + (idx >> 7), n = idx & 127;
            if (k >= Kpad) continue;
            float v = (k < Kdim) ? W[(size_t)k * HDIM + n] : 0.f;
            dst[bfrag_off(k, n)] = f2tf32(v);
        }
    } else {
        const int bb = b - 32;
        const int slot = bb >> 3;           // 0..2 -> W1..W3 (Kdim=128)
        const int chunk = bb & 7;           // k16 index
        const float* W = (slot == 0) ? W1 : (slot == 1) ? W2 : W3;
        uint32_t* dst = g_wfrag + 32768 + slot * 8192;
#pragma unroll
        for (int i = 0; i < 4; i++) {
            int w = chunk * 1024 + threadIdx.x + i * 256;
            int nt   = (w >> 6) & 15;
            int widx = w & 63;
            int reg  = widx & 1;
            int lane = widx >> 1;
            int n  = nt * 8 + (lane >> 2);
            int tg = lane & 3;
            int k  = chunk * 16 + tg * 2 + reg * 8;
            dst[w] = packh2(W[(size_t)k * HDIM + n], W[(size_t)(k + 1) * HDIM + n]);
        }
    }
}

// ---------------------------------------------------------------------------
// Input-transform GEMM (fp32 A): tf32 m16n8k8, R9 structure, fp16 output.
// out = A @ W + bias, stored as __half. STRIDE = KPAD+4 (%8==4: conflict-free).
// ---------------------------------------------------------------------------
template<int KDIM, int KPAD>
__global__ __launch_bounds__(256, 2) void k_gemm_f32in(
    const float* __restrict__ A, int M,
    const uint32_t* __restrict__ Bfrag, const float* __restrict__ bias,
    __half* __restrict__ out)
{
    constexpr int STRIDE = KPAD + 4;
    constexpr int K8 = KPAD / 8;
    extern __shared__ uint32_t sA[];

    const int tid = threadIdx.x;
    const int wid = tid >> 5;
    const int lane = tid & 31;
    const int m0 = blockIdx.x * 128;
    const int wm = wid & 3;
    const int wn = wid >> 2;
    const int g = lane >> 2, tg = lane & 3;

    constexpr int NC4 = KPAD / 4;
#pragma unroll
    for (int it = 0; it < 128 * NC4 / 256; it++) {
        int idx4 = tid + it * 256;
        int r = idx4 / NC4;
        int c4 = (idx4 - r * NC4) * 4;
        int gm = m0 + r;
        float4 v = make_float4(0.f, 0.f, 0.f, 0.f);
        if (gm < M && c4 < KDIM)
            v = *(const float4*)&A[(size_t)gm * KDIM + c4];
        uint32_t* p = sA + r * STRIDE + c4;
        p[0] = f2tf32(v.x); p[1] = f2tf32(v.y);
        p[2] = f2tf32(v.z); p[3] = f2tf32(v.w);
    }
    __syncthreads();

    float acc[2][8][4];
#pragma unroll
    for (int mt = 0; mt < 2; mt++)
#pragma unroll
        for (int nt = 0; nt < 8; nt++)
#pragma unroll
            for (int j = 0; j < 4; j++) acc[mt][nt][j] = 0.f;

    const uint32_t* sAr = sA + (wm * 32 + g) * STRIDE + tg;
    const uint2* Bw = (const uint2*)(Bfrag + (wn * 8) * 64) + lane;

#pragma unroll
    for (int k8 = 0; k8 < K8; k8++) {
        const int c0 = k8 * 8;
        uint32_t a[2][4];
#pragma unroll
        for (int mt = 0; mt < 2; mt++) {
            const uint32_t* p = sAr + mt * 16 * STRIDE;
            a[mt][0] = p[c0];
            a[mt][1] = p[8 * STRIDE + c0];
            a[mt][2] = p[c0 + 4];
            a[mt][3] = p[8 * STRIDE + c0 + 4];
        }
        uint32_t b[8][2];
#pragma unroll
        for (int nt = 0; nt < 8; nt++) {
            uint2 t = Bw[(k8 * 16 + nt) * 32];
            b[nt][0] = t.x; b[nt][1] = t.y;
        }
#pragma unroll
        for (int mt = 0; mt < 2; mt++)
#pragma unroll
            for (int nt = 0; nt < 8; nt++)
                mma_tf32(acc[mt][nt], a[mt], b[nt]);
    }

    const int rbase = m0 + wm * 32 + g;
#pragma unroll
    for (int mt = 0; mt < 2; mt++) {
        int r0 = rbase + mt * 16;
        int r1 = r0 + 8;
#pragma unroll
        for (int nt = 0; nt < 8; nt++) {
            int col = wn * 64 + nt * 8 + tg * 2;
            float2 bb = *(const float2*)&bias[col];
            if (r0 < M)
                *(__half2*)&out[(size_t)r0 * HDIM + col] =
                    __floats2half2_rn(acc[mt][nt][0] + bb.x, acc[mt][nt][1] + bb.y);
            if (r1 < M)
                *(__half2*)&out[(size_t)r1 * HDIM + col] =
                    __floats2half2_rn(acc[mt][nt][2] + bb.x, acc[mt][nt][3] + bb.y);
        }
    }
}

// ---------------------------------------------------------------------------
// Layer GEMM (fp16 A = g_x): f16 m16n8k16, K=128. A staged as raw fp16 copy
// (LDG.128 -> STS.128). Row stride 68 words (%8==4: conflict-free LDS.32).
// out = A @ W stored fp16 -> g_y.
// ---------------------------------------------------------------------------
__global__ __launch_bounds__(256, 2) void k_gemm_h16(
    const __half* __restrict__ A, int M,
    const uint32_t* __restrict__ Bfrag, __half* __restrict__ out)
{
    constexpr int SW = 68;                 // words per row (64 data + 4 pad)
    __shared__ uint32_t sA[128 * SW];      // 34816 B

    const int tid = threadIdx.x;
    const int wid = tid >> 5;
    const int lane = tid & 31;
    const int m0 = blockIdx.x * 128;
    const int wm = wid & 3;
    const int wn = wid >> 2;
    const int g = lane >> 2, tg = lane & 3;

    // stage A: 128 rows x 128 halves; uint4 = 8 halves; 16 uint4/row
#pragma unroll
    for (int it = 0; it < 8; it++) {
        int idx = tid + it * 256;
        int r = idx >> 4, u = idx & 15;
        int gm = m0 + r;
        uint4 v = make_uint4(0u, 0u, 0u, 0u);
        if (gm < M) v = *(const uint4*)&A[(size_t)gm * HDIM + u * 8];
        *(uint4*)(sA + r * SW + u * 4) = v;
    }
    __syncthreads();

    float acc[2][8][4];
#pragma unroll
    for (int mt = 0; mt < 2; mt++)
#pragma unroll
        for (int nt = 0; nt < 8; nt++)
#pragma unroll
            for (int j = 0; j < 4; j++) acc[mt][nt][j] = 0.f;

    const uint32_t* sAr = sA + (wm * 32 + g) * SW + tg;
    const uint2* Bw = (const uint2*)(Bfrag + (wn * 8) * 64) + lane;

#pragma unroll
    for (int k16 = 0; k16 < 8; k16++) {
        const int c0 = k16 * 8;            // word offset (16 halves = 8 words)
        uint32_t a[2][4];
#pragma unroll
        for (int mt = 0; mt < 2; mt++) {
            const uint32_t* p = sAr + mt * 16 * SW;
            a[mt][0] = p[c0];
            a[mt][1] = p[8 * SW + c0];
            a[mt][2] = p[c0 + 4];
            a[mt][3] = p[8 * SW + c0 + 4];
        }
        uint32_t b[8][2];
#pragma unroll
        for (int nt = 0; nt < 8; nt++) {
            uint2 t = Bw[(k16 * 16 + nt) * 32];
            b[nt][0] = t.x; b[nt][1] = t.y;
        }
#pragma unroll
        for (int mt = 0; mt < 2; mt++)
#pragma unroll
            for (int nt = 0; nt < 8; nt++)
                mma_f16(acc[mt][nt], a[mt], b[nt]);
    }

    const int rbase = m0 + wm * 32 + g;
#pragma unroll
    for (int mt = 0; mt < 2; mt++) {
        int r0 = rbase + mt * 16;
        int r1 = r0 + 8;
#pragma unroll
        for (int nt = 0; nt < 8; nt++) {
            int col = wn * 64 + nt * 8 + tg * 2;
            if (r0 < M)
                *(__half2*)&out[(size_t)r0 * HDIM + col] =
                    __floats2half2_rn(acc[mt][nt][0], acc[mt][nt][1]);
            if (r1 < M)
                *(__half2*)&out[(size_t)r1 * HDIM + col] =
                    __floats2half2_rn(acc[mt][nt][2], acc[mt][nt][3]);
        }
    }
}

// ---------------------------------------------------------------------------
// Edge dtype detect + CSR build
// ---------------------------------------------------------------------------
__global__ void k_detect(const void* __restrict__ edges) {
    if (threadIdx.x == 0 && blockIdx.x == 0) {
        const unsigned int* w = (const unsigned int*)edges;
        int is64 = 1;
        for (int i = 0; i < 64; i++)
            if (w[2 * i + 1] != 0u) { is64 = 0; break; }
        g_is64 = is64;
    }
}
__global__ void k_zero() {
    int i = blockIdx.x * blockDim.x + threadIdx.x;
    if (i < NN) g_deg[i] = 0;
}
__device__ __forceinline__ void load_edge(const void* edges, int i, int& s, int& d) {
    if (g_is64) {
        const long long* e = (const long long*)edges;
        s = (int)e[i]; d = (int)e[NE + i];
    } else {
        const int* e = (const int*)edges;
        s = e[i]; d = e[NE + i];
    }
}
__global__ void k_hist(const void* __restrict__ edges) {
    int i = blockIdx.x * blockDim.x + threadIdx.x;
    if (i >= NE) return;
    int s, d; load_edge(edges, i, s, d);
    atomicAdd(&g_deg[d], 1);
}
__global__ __launch_bounds__(256) void k_scan1() {
    __shared__ int wsum[8], wbase[8];
    int b = blockIdx.x, tid = threadIdx.x;
    int base = b * 1024 + tid * 4;
    int v0 = 0, v1 = 0, v2 = 0, v3 = 0;
    if (base + 3 < NN) {
        int4 t = *(const int4*)&g_deg[base];
        v0 = t.x; v1 = t.y; v2 = t.z; v3 = t.w;
    } else {
        if (base + 0 < NN) v0 = g_deg[base + 0];
        if (base + 1 < NN) v1 = g_deg[base + 1];
        if (base + 2 < NN) v2 = g_deg[base + 2];
        if (base + 3 < NN) v3 = g_deg[base + 3];
    }
    int s = v0 + v1 + v2 + v3;
    int lane = tid & 31, w = tid >> 5;
    int x = s;
#pragma unroll
    for (int off = 1; off < 32; off <<= 1) {
        int t = __shfl_up_sync(0xffffffffu, x, off);
        if (lane >= off) x += t;
    }
    if (lane == 31) wsum[w] = x;
    __syncthreads();
    if (tid == 0) {
        int run = 0;
#pragma unroll
        for (int i = 0; i < 8; i++) { wbase[i] = run; run += wsum[i]; }
        g_blksum[b] = run;
    }
    __syncthreads();
    int ex = wbase[w] + x - s;
    if (base + 0 < NN) g_rowstart[base + 0] = ex;
    if (base + 1 < NN) g_rowstart[base + 1] = ex + v0;
    if (base + 2 < NN) g_rowstart[base + 2] = ex + v0 + v1;
    if (base + 3 < NN) g_rowstart[base + 3] = ex + v0 + v1 + v2;
}
__global__ __launch_bounds__(128) void k_scan2() {
    __shared__ int sh[NBLK1];
    int tid = threadIdx.x;
    if (tid < NBLK1) sh[tid] = g_blksum[tid];
    __syncthreads();
    if (tid == 0) {
        int run = 0;
        for (int i = 0; i < NBLK1; i++) { int t = sh[i]; sh[i] = run; run += t; }
    }
    __syncthreads();
    if (tid < NBLK1) g_blksum[tid] = sh[tid];
}
__global__ void k_scan3() {
    int i = blockIdx.x * blockDim.x + threadIdx.x;
    if (i >= NN) return;
    int rs = g_rowstart[i] + g_blksum[i >> 10];
    g_rowstart[i] = rs;
    g_cursor[i] = rs;
    g_dinv[i] = rsqrtf((float)g_deg[i] + 1.0f);
    if (i == 0) g_rowstart[NN] = NE;
}
__global__ void k_fill(const void* __restrict__ edges) {
    int i = blockIdx.x * blockDim.x + threadIdx.x;
    if (i >= NE) return;
    int s, d; load_edge(edges, i, s, d);
    int pos = atomicAdd(&g_cursor[d], 1);
    g_esrc[pos] = s;
}

// ---------------------------------------------------------------------------
// CSR gather + fused ReLU, fp16 in/out. Lane covers cols lane*4..lane*4+3.
// ---------------------------------------------------------------------------
__device__ __forceinline__ void h4_to_f4(uint2 t, float4& f) {
    float2 a = __half22float2(*reinterpret_cast<__half2*>(&t.x));
    float2 b = __half22float2(*reinterpret_cast<__half2*>(&t.y));
    f.x = a.x; f.y = a.y; f.z = b.x; f.w = b.y;
}
__global__ __launch_bounds__(256) void k_gather(const float* __restrict__ bias) {
    int gt = blockIdx.x * blockDim.x + threadIdx.x;
    int node = gt >> 5;
    int lane = gt & 31;
    if (node >= NN) return;

    const int co = lane * 4;
    float dd = g_dinv[node];
    float4 acc;
    {
        uint2 t = *(const uint2*)&g_y[(size_t)node * HDIM + co];
        h4_to_f4(t, acc);
        acc.x *= dd; acc.y *= dd; acc.z *= dd; acc.w *= dd;
    }

    int e = g_rowstart[node];
    const int end = g_rowstart[node + 1];
    for (; e + 4 <= end; e += 4) {
        int s0 = g_esrc[e], s1 = g_esrc[e + 1], s2 = g_esrc[e + 2], s3 = g_esrc[e + 3];
        float n0 = g_dinv[s0], n1 = g_dinv[s1], n2 = g_dinv[s2], n3 = g_dinv[s3];
        uint2 t0 = *(const uint2*)&g_y[(size_t)s0 * HDIM + co];
        uint2 t1 = *(const uint2*)&g_y[(size_t)s1 * HDIM + co];
        uint2 t2 = *(const uint2*)&g_y[(size_t)s2 * HDIM + co];
        uint2 t3 = *(const uint2*)&g_y[(size_t)s3 * HDIM + co];
        float4 a, b, c, d;
        h4_to_f4(t0, a); h4_to_f4(t1, b); h4_to_f4(t2, c); h4_to_f4(t3, d);
        acc.x += a.x * n0 + b.x * n1 + c.x * n2 + d.x * n3;
        acc.y += a.y * n0 + b.y * n1 + c.y * n2 + d.y * n3;
        acc.z += a.z * n0 + b.z * n1 + c.z * n2 + d.z * n3;
        acc.w += a.w * n0 + b.w * n1 + c.w * n2 + d.w * n3;
    }
    for (; e < end; e++) {
        int s = g_esrc[e];
        float ns = g_dinv[s];
        uint2 t = *(const uint2*)&g_y[(size_t)s * HDIM + co];
        float4 a; h4_to_f4(t, a);
        acc.x += a.x * ns; acc.y += a.y * ns; acc.z += a.z * ns; acc.w += a.w * ns;
    }
    float4 bb = *(const float4*)&bias[co];
    float ox = fmaxf(acc.x * dd + bb.x, 0.f);
    float oy = fmaxf(acc.y * dd + bb.y, 0.f);
    float oz = fmaxf(acc.z * dd + bb.z, 0.f);
    float ow = fmaxf(acc.w * dd + bb.w, 0.f);
    uint2 o;
    *reinterpret_cast<__half2*>(&o.x) = __floats2half2_rn(ox, oy);
    *reinterpret_cast<__half2*>(&o.y) = __floats2half2_rn(oz, ow);
    *(uint2*)&g_x[(size_t)node * HDIM + co] = o;
}

// ---------------------------------------------------------------------------
// Output GEMM: out[NN,16] = g_x @ Wo + bo   (g_x fp16, already relu'd)
// ---------------------------------------------------------------------------
__global__ __launch_bounds__(256) void k_out(
    const float* __restrict__ Wo, const float* __restrict__ bo,
    float* __restrict__ out)
{
    __shared__ float sX[64][HDIM];
    __shared__ float sW[HDIM][ODIM];
    const int tid = threadIdx.x;
    const int m0 = blockIdx.x * 64;

#pragma unroll
    for (int it = 0; it < 8; it++) {
        int idx = tid + it * 256;
        int r = idx >> 5;
        int c4 = (idx & 31) * 4;
        int gm = m0 + r;
        float4 v = make_float4(0.f, 0.f, 0.f, 0.f);
        if (gm < NN) {
            uint2 t = *(const uint2*)&g_x[(size_t)gm * HDIM + c4];
            h4_to_f4(t, v);
        }
        *(float4*)&sX[r][c4] = v;
    }
#pragma unroll
    for (int it = 0; it < 8; it++) {
        int idx = tid + it * 256;
        ((float*)sW)[idx] = Wo[idx];
    }
    __syncthreads();

    const int col = tid & 15;
    const int r0 = (tid >> 4) * 4;
    float acc[4] = {0.f, 0.f, 0.f, 0.f};
#pragma unroll 4
    for (int k = 0; k < HDIM; k++) {
        float w = sW[k][col];
        acc[0] += sX[r0 + 0][k] * w;
        acc[1] += sX[r0 + 1][k] * w;
        acc[2] += sX[r0 + 2][k] * w;
        acc[3] += sX[r0 + 3][k] * w;
    }
    float bb = bo[col];
#pragma unroll
    for (int i = 0; i < 4; i++) {
        int gm = m0 + r0 + i;
        if (gm < NN) out[(size_t)gm * ODIM + col] = acc[i] + bb;
    }
}

// ---------------------------------------------------------------------------
extern "C" void kernel_launch(void* const* d_in, const int* in_sizes, int n_in,
                              void* d_out, int out_size) {
    const float* user = (const float*)d_in[0];
    const float* prod = (const float*)d_in[1];
    const void*  edges = d_in[2];
    const float* Wu = (const float*)d_in[3];
    const float* bu = (const float*)d_in[4];
    const float* Wp = (const float*)d_in[5];
    const float* bp = (const float*)d_in[6];
    const float* W1 = (const float*)d_in[7];
    const float* b1 = (const float*)d_in[8];
    const float* W2 = (const float*)d_in[9];
    const float* b2 = (const float*)d_in[10];
    const float* W3 = (const float*)d_in[11];
    const float* b3 = (const float*)d_in[12];
    const float* Wo = (const float*)d_in[13];
    const float* bo = (const float*)d_in[14];
    float* out = (float*)d_out;

    __half *px = nullptr, *py = nullptr;
    uint32_t* pw = nullptr;
    cudaGetSymbolAddress((void**)&px, g_x);
    cudaGetSymbolAddress((void**)&py, g_y);
    cudaGetSymbolAddress((void**)&pw, g_wfrag);

    const int smem64  = 128 * (64 + 4) * 4;    // 34816
    const int smem104 = 128 * (104 + 4) * 4;   // 55296
    cudaFuncSetAttribute(k_gemm_f32in<64, 64>,   cudaFuncAttributeMaxDynamicSharedMemorySize, smem64);
    cudaFuncSetAttribute(k_gemm_f32in<100, 104>, cudaFuncAttributeMaxDynamicSharedMemorySize, smem104);

    // 1: B fragments (tf32 for inputs, f16 for layers)
    k_wfrag<<<56, 256>>>(Wu, Wp, W1, W2, W3);

    // 2-3: input transforms -> g_x (fp16; bias added; no relu: conv1 input)
    k_gemm_f32in<64, 64><<<(N_USERS + 127) / 128, 256, smem64>>>(
        user, N_USERS, pw + 0 * 16384, bu, px);
    k_gemm_f32in<100, 104><<<(N_PRODS + 127) / 128, 256, smem104>>>(
        prod, N_PRODS, pw + 1 * 16384, bp, px + (size_t)N_USERS * HDIM);

    // 4: layer-1 GEMM (profiled slot #4)
    k_gemm_h16<<<(NN + 127) / 128, 256>>>(px, NN, pw + 32768 + 0 * 8192, py);

    // 5-11: CSR build (independent of GEMMs above)
    k_detect<<<1, 32>>>(edges);
    k_zero<<<(NN + 255) / 256, 256>>>();
    k_hist<<<(NE + 255) / 256, 256>>>(edges);
    k_scan1<<<NBLK1, 256>>>();
    k_scan2<<<1, 128>>>();
    k_scan3<<<(NN + 255) / 256, 256>>>();
    k_fill<<<(NE + 255) / 256, 256>>>(edges);

    // layer 1 gather (+relu)
    k_gather<<<(NN * 32 + 255) / 256, 256>>>(b1);

    // layers 2,3
    k_gemm_h16<<<(NN + 127) / 128, 256>>>(px, NN, pw + 32768 + 1 * 8192, py);
    k_gather<<<(NN * 32 + 255) / 256, 256>>>(b2);

    k_gemm_h16<<<(NN + 127) / 128, 256>>>(px, NN, pw + 32768 + 2 * 8192, py);
    k_gather<<<(NN * 32 + 255) / 256, 256>>>(b3);

    k_out<<<(NN + 63) / 64, 256>>>(Wo, bo, out);
}

// round 11
// speedup vs baseline: 1.9378x; 1.0855x over previous
#include <cuda_runtime.h>
#include <cuda_fp16.h>
#include <cstdint>
#include <cstddef>

#define N_USERS 50000
#define N_PRODS 50000
#define NN      100000
#define NE      600000
#define HDIM    128
#define ODIM    16
#define NBLK1   98        // ceil(NN/1024)

// Scratch (__device__ globals: allocation-free rule)
__device__ __half   g_x[(size_t)NN * HDIM];
__device__ __half   g_y[(size_t)NN * HDIM];
__device__ float    g_dinv[NN];
__device__ int      g_deg[NN];
__device__ int      g_rowstart[NN + 1];
__device__ int      g_cursor[NN];
__device__ int      g_esrc[NE];
__device__ int      g_blksum[NBLK1];
__device__ int      g_is64;
// f16 B fragments: Wu@0(4096), Wp@4096(7168), W1@11264, W2@19456, W3@27648 (8192 ea), Wo@35840(1024)
__device__ uint32_t g_wfrag[36864];

#define OFF_WU 0
#define OFF_WP 4096
#define OFF_W1 11264
#define OFF_W2 19456
#define OFF_W3 27648
#define OFF_WO 35840

// ---------------------------------------------------------------------------
// helpers (sm_80-class PTX only)
// ---------------------------------------------------------------------------
__device__ __forceinline__ uint32_t packh2(float lo, float hi) {
    __half2 h = __floats2half2_rn(lo, hi);
    return *reinterpret_cast<uint32_t*>(&h);
}
__device__ __forceinline__ void mma_f16(float* c, const uint32_t* a, const uint32_t* b) {
    asm volatile(
        "mma.sync.aligned.m16n8k16.row.col.f32.f16.f16.f32 "
        "{%0,%1,%2,%3}, {%4,%5,%6,%7}, {%8,%9}, {%0,%1,%2,%3};"
        : "+f"(c[0]), "+f"(c[1]), "+f"(c[2]), "+f"(c[3])
        : "r"(a[0]), "r"(a[1]), "r"(a[2]), "r"(a[3]), "r"(b[0]), "r"(b[1]));
}

// ---------------------------------------------------------------------------
// Precompute f16 B fragments for all 6 weights (Wu,Wp,W1,W2,W3 @N=128; Wo @N=16).
// m16n8k16 B tile word w: reg=w&1, lane=w>>1, n'=lane>>2, tg=lane&3;
// word = {B[tg*2+reg*8][n'], B[tg*2+1+reg*8][n']}. Tile (k16,nt) at (k16*NT+nt)*64.
// ---------------------------------------------------------------------------
__global__ __launch_bounds__(256) void k_wfrag(
    const float* __restrict__ Wu, const float* __restrict__ Wp,
    const float* __restrict__ W1, const float* __restrict__ W2,
    const float* __restrict__ W3, const float* __restrict__ Wo)
{
    const int nblk[6] = {4, 7, 8, 8, 8, 1};
    const int offs[6] = {OFF_WU, OFF_WP, OFF_W1, OFF_W2, OFF_W3, OFF_WO};
    const int kds[6]  = {64, 100, 128, 128, 128, 128};
    int b = blockIdx.x, slot = 0;
    while (slot < 6 && b >= nblk[slot]) { b -= nblk[slot]; slot++; }
    if (slot >= 6) return;
    const float* W = (slot == 0) ? Wu : (slot == 1) ? Wp : (slot == 2) ? W1
                   : (slot == 3) ? W2 : (slot == 4) ? W3 : Wo;
    const int Kdim = kds[slot];
    uint32_t* dst = g_wfrag + offs[slot];
    if (slot < 5) {
#pragma unroll
        for (int i = 0; i < 4; i++) {
            int w = b * 1024 + threadIdx.x + i * 256;
            int nt = (w >> 6) & 15;
            int widx = w & 63;
            int reg = widx & 1, lane = widx >> 1;
            int n = nt * 8 + (lane >> 2), tg = lane & 3;
            int k = (w >> 10) * 16 + tg * 2 + reg * 8;
            float lo = (k     < Kdim) ? W[(size_t)k * HDIM + n] : 0.f;
            float hi = (k + 1 < Kdim) ? W[(size_t)(k + 1) * HDIM + n] : 0.f;
            dst[w] = packh2(lo, hi);
        }
    } else {
        // Wo: 128x16, 8 k16 x 2 nt
#pragma unroll
        for (int i = 0; i < 4; i++) {
            int w = threadIdx.x + i * 256;
            int k16 = w >> 7, r = w & 127;
            int nt = (r >> 6) & 1;
            int widx = r & 63;
            int reg = widx & 1, lane = widx >> 1;
            int n = nt * 8 + (lane >> 2), tg = lane & 3;
            int k = k16 * 16 + tg * 2 + reg * 8;
            dst[w] = packh2(W[(size_t)k * ODIM + n], W[(size_t)(k + 1) * ODIM + n]);
        }
    }
}

// ---------------------------------------------------------------------------
// Unified f16 m16n8k16 GEMM: 256 thr, 128x128 CTA tile, warp tile 32x64.
// F32IN: stage fp32 A (lda=KDIM) -> packed f16 SMEM. else raw fp16 copy (lda=128).
// SMEM row stride SW words, SW%8==4 -> conflict-free LDS.32 fragment reads.
// out fp16; optional bias (nullptr for layer GEMMs).
// ---------------------------------------------------------------------------
template<int K16, int SW, bool F32IN, int KDIM>
__global__ __launch_bounds__(256, 2) void k_gemm(
    const void* __restrict__ Av, int M,
    const uint32_t* __restrict__ Bfrag, const float* __restrict__ bias,
    __half* __restrict__ out)
{
    __shared__ uint32_t sA[128 * SW];

    const int tid = threadIdx.x;
    const int wid = tid >> 5;
    const int lane = tid & 31;
    const int m0 = blockIdx.x * 128;
    const int wm = wid & 3;
    const int wn = wid >> 2;
    const int g = lane >> 2, tg = lane & 3;

    if (F32IN) {
        const float* A = (const float*)Av;
        constexpr int KPAD = K16 * 16;
        constexpr int NC4 = KPAD / 4;
#pragma unroll
        for (int it = 0; it < 128 * NC4 / 256; it++) {
            int idx4 = tid + it * 256;
            int r = idx4 / NC4;
            int c4 = (idx4 - r * NC4) * 4;
            int gm = m0 + r;
            float4 v = make_float4(0.f, 0.f, 0.f, 0.f);
            if (gm < M && c4 < KDIM)
                v = *(const float4*)&A[(size_t)gm * KDIM + c4];
            uint32_t* p = sA + r * SW + c4 / 2;
            p[0] = packh2(v.x, v.y);
            p[1] = packh2(v.z, v.w);
        }
    } else {
        const __half* A = (const __half*)Av;
#pragma unroll
        for (int it = 0; it < 8; it++) {
            int idx = tid + it * 256;
            int r = idx >> 4, u = idx & 15;
            int gm = m0 + r;
            uint4 v = make_uint4(0u, 0u, 0u, 0u);
            if (gm < M) v = *(const uint4*)&A[(size_t)gm * HDIM + u * 8];
            *(uint4*)(sA + r * SW + u * 4) = v;
        }
    }
    __syncthreads();

    float acc[2][8][4];
#pragma unroll
    for (int mt = 0; mt < 2; mt++)
#pragma unroll
        for (int nt = 0; nt < 8; nt++)
#pragma unroll
            for (int j = 0; j < 4; j++) acc[mt][nt][j] = 0.f;

    const uint32_t* sAr = sA + (wm * 32 + g) * SW + tg;
    const uint2* Bw = (const uint2*)(Bfrag + (wn * 8) * 64) + lane;

#pragma unroll
    for (int k16 = 0; k16 < K16; k16++) {
        const int c0 = k16 * 8;
        uint32_t a[2][4];
#pragma unroll
        for (int mt = 0; mt < 2; mt++) {
            const uint32_t* p = sAr + mt * 16 * SW;
            a[mt][0] = p[c0];
            a[mt][1] = p[8 * SW + c0];
            a[mt][2] = p[c0 + 4];
            a[mt][3] = p[8 * SW + c0 + 4];
        }
        uint32_t b[8][2];
#pragma unroll
        for (int nt = 0; nt < 8; nt++) {
            uint2 t = Bw[(k16 * 16 + nt) * 32];
            b[nt][0] = t.x; b[nt][1] = t.y;
        }
#pragma unroll
        for (int mt = 0; mt < 2; mt++)
#pragma unroll
            for (int nt = 0; nt < 8; nt++)
                mma_f16(acc[mt][nt], a[mt], b[nt]);
    }

    const int rbase = m0 + wm * 32 + g;
#pragma unroll
    for (int mt = 0; mt < 2; mt++) {
        int r0 = rbase + mt * 16;
        int r1 = r0 + 8;
#pragma unroll
        for (int nt = 0; nt < 8; nt++) {
            int col = wn * 64 + nt * 8 + tg * 2;
            float bx = 0.f, by = 0.f;
            if (bias) {
                float2 bb = *(const float2*)&bias[col];
                bx = bb.x; by = bb.y;
            }
            if (r0 < M)
                *(__half2*)&out[(size_t)r0 * HDIM + col] =
                    __floats2half2_rn(acc[mt][nt][0] + bx, acc[mt][nt][1] + by);
            if (r1 < M)
                *(__half2*)&out[(size_t)r1 * HDIM + col] =
                    __floats2half2_rn(acc[mt][nt][2] + bx, acc[mt][nt][3] + by);
        }
    }
}

// ---------------------------------------------------------------------------
// Edge detect + degree zero (merged) + CSR build
// ---------------------------------------------------------------------------
__global__ void k_prep(const void* __restrict__ edges) {
    int i = blockIdx.x * blockDim.x + threadIdx.x;
    if (i < NN) g_deg[i] = 0;
    if (i == 0) {
        const unsigned int* w = (const unsigned int*)edges;
        int is64 = 1;
        for (int j = 0; j < 64; j++)
            if (w[2 * j + 1] != 0u) { is64 = 0; break; }
        g_is64 = is64;
    }
}
__device__ __forceinline__ void load_edge(const void* edges, int i, int& s, int& d) {
    if (g_is64) {
        const long long* e = (const long long*)edges;
        s = (int)e[i]; d = (int)e[NE + i];
    } else {
        const int* e = (const int*)edges;
        s = e[i]; d = e[NE + i];
    }
}
__global__ void k_hist(const void* __restrict__ edges) {
    int i = blockIdx.x * blockDim.x + threadIdx.x;
    if (i >= NE) return;
    int s, d; load_edge(edges, i, s, d);
    atomicAdd(&g_deg[d], 1);
}
__global__ __launch_bounds__(256) void k_scan1() {
    __shared__ int wsum[8], wbase[8];
    int b = blockIdx.x, tid = threadIdx.x;
    int base = b * 1024 + tid * 4;
    int v0 = 0, v1 = 0, v2 = 0, v3 = 0;
    if (base + 3 < NN) {
        int4 t = *(const int4*)&g_deg[base];
        v0 = t.x; v1 = t.y; v2 = t.z; v3 = t.w;
    } else {
        if (base + 0 < NN) v0 = g_deg[base + 0];
        if (base + 1 < NN) v1 = g_deg[base + 1];
        if (base + 2 < NN) v2 = g_deg[base + 2];
        if (base + 3 < NN) v3 = g_deg[base + 3];
    }
    int s = v0 + v1 + v2 + v3;
    int lane = tid & 31, w = tid >> 5;
    int x = s;
#pragma unroll
    for (int off = 1; off < 32; off <<= 1) {
        int t = __shfl_up_sync(0xffffffffu, x, off);
        if (lane >= off) x += t;
    }
    if (lane == 31) wsum[w] = x;
    __syncthreads();
    if (tid == 0) {
        int run = 0;
#pragma unroll
        for (int i = 0; i < 8; i++) { wbase[i] = run; run += wsum[i]; }
        g_blksum[b] = run;
    }
    __syncthreads();
    int ex = wbase[w] + x - s;
    if (base + 0 < NN) g_rowstart[base + 0] = ex;
    if (base + 1 < NN) g_rowstart[base + 1] = ex + v0;
    if (base + 2 < NN) g_rowstart[base + 2] = ex + v0 + v1;
    if (base + 3 < NN) g_rowstart[base + 3] = ex + v0 + v1 + v2;
}
__global__ __launch_bounds__(128) void k_scan2() {
    __shared__ int sh[NBLK1];
    int tid = threadIdx.x;
    if (tid < NBLK1) sh[tid] = g_blksum[tid];
    __syncthreads();
    if (tid == 0) {
        int run = 0;
        for (int i = 0; i < NBLK1; i++) { int t = sh[i]; sh[i] = run; run += t; }
    }
    __syncthreads();
    if (tid < NBLK1) g_blksum[tid] = sh[tid];
}
__global__ void k_scan3() {
    int i = blockIdx.x * blockDim.x + threadIdx.x;
    if (i >= NN) return;
    int rs = g_rowstart[i] + g_blksum[i >> 10];
    g_rowstart[i] = rs;
    g_cursor[i] = rs;
    g_dinv[i] = rsqrtf((float)g_deg[i] + 1.0f);
    if (i == 0) g_rowstart[NN] = NE;
}
__global__ void k_fill(const void* __restrict__ edges) {
    int i = blockIdx.x * blockDim.x + threadIdx.x;
    if (i >= NE) return;
    int s, d; load_edge(edges, i, s, d);
    int pos = atomicAdd(&g_cursor[d], 1);
    g_esrc[pos] = s;
}

// ---------------------------------------------------------------------------
// CSR gather + fused ReLU, fp16 in/out. Lane covers cols lane*4..lane*4+3.
// ---------------------------------------------------------------------------
__device__ __forceinline__ void h4_to_f4(uint2 t, float4& f) {
    float2 a = __half22float2(*reinterpret_cast<__half2*>(&t.x));
    float2 b = __half22float2(*reinterpret_cast<__half2*>(&t.y));
    f.x = a.x; f.y = a.y; f.z = b.x; f.w = b.y;
}
__global__ __launch_bounds__(256) void k_gather(const float* __restrict__ bias) {
    int gt = blockIdx.x * blockDim.x + threadIdx.x;
    int node = gt >> 5;
    int lane = gt & 31;
    if (node >= NN) return;

    const int co = lane * 4;
    float dd = g_dinv[node];
    float4 acc;
    {
        uint2 t = *(const uint2*)&g_y[(size_t)node * HDIM + co];
        h4_to_f4(t, acc);
        acc.x *= dd; acc.y *= dd; acc.z *= dd; acc.w *= dd;
    }

    int e = g_rowstart[node];
    const int end = g_rowstart[node + 1];
    for (; e + 4 <= end; e += 4) {
        int s0 = g_esrc[e], s1 = g_esrc[e + 1], s2 = g_esrc[e + 2], s3 = g_esrc[e + 3];
        float n0 = g_dinv[s0], n1 = g_dinv[s1], n2 = g_dinv[s2], n3 = g_dinv[s3];
        uint2 t0 = *(const uint2*)&g_y[(size_t)s0 * HDIM + co];
        uint2 t1 = *(const uint2*)&g_y[(size_t)s1 * HDIM + co];
        uint2 t2 = *(const uint2*)&g_y[(size_t)s2 * HDIM + co];
        uint2 t3 = *(const uint2*)&g_y[(size_t)s3 * HDIM + co];
        float4 a, b, c, d;
        h4_to_f4(t0, a); h4_to_f4(t1, b); h4_to_f4(t2, c); h4_to_f4(t3, d);
        acc.x += a.x * n0 + b.x * n1 + c.x * n2 + d.x * n3;
        acc.y += a.y * n0 + b.y * n1 + c.y * n2 + d.y * n3;
        acc.z += a.z * n0 + b.z * n1 + c.z * n2 + d.z * n3;
        acc.w += a.w * n0 + b.w * n1 + c.w * n2 + d.w * n3;
    }
    for (; e < end; e++) {
        int s = g_esrc[e];
        float ns = g_dinv[s];
        uint2 t = *(const uint2*)&g_y[(size_t)s * HDIM + co];
        float4 a; h4_to_f4(t, a);
        acc.x += a.x * ns; acc.y += a.y * ns; acc.z += a.z * ns; acc.w += a.w * ns;
    }
    float4 bb = *(const float4*)&bias[co];
    float ox = fmaxf(acc.x * dd + bb.x, 0.f);
    float oy = fmaxf(acc.y * dd + bb.y, 0.f);
    float oz = fmaxf(acc.z * dd + bb.z, 0.f);
    float ow = fmaxf(acc.w * dd + bb.w, 0.f);
    uint2 o;
    *reinterpret_cast<__half2*>(&o.x) = __floats2half2_rn(ox, oy);
    *reinterpret_cast<__half2*>(&o.y) = __floats2half2_rn(oz, ow);
    *(uint2*)&g_x[(size_t)node * HDIM + co] = o;
}

// ---------------------------------------------------------------------------
// Output GEMM (f16 mma): out[NN,16] = g_x @ Wo + bo.
// CTA 128 rows, 8 warps, warp tile 16x16. Same conflict-free staging (SW=68).
// ---------------------------------------------------------------------------
__global__ __launch_bounds__(256) void k_out(
    const uint32_t* __restrict__ Bfrag, const float* __restrict__ bo,
    float* __restrict__ out)
{
    constexpr int SW = 68;
    __shared__ uint32_t sA[128 * SW];
    const int tid = threadIdx.x;
    const int wid = tid >> 5;
    const int lane = tid & 31;
    const int m0 = blockIdx.x * 128;
    const int g = lane >> 2, tg = lane & 3;

#pragma unroll
    for (int it = 0; it < 8; it++) {
        int idx = tid + it * 256;
        int r = idx >> 4, u = idx & 15;
        int gm = m0 + r;
        uint4 v = make_uint4(0u, 0u, 0u, 0u);
        if (gm < NN) v = *(const uint4*)&g_x[(size_t)gm * HDIM + u * 8];
        *(uint4*)(sA + r * SW + u * 4) = v;
    }
    __syncthreads();

    float acc[2][4];
#pragma unroll
    for (int nt = 0; nt < 2; nt++)
#pragma unroll
        for (int j = 0; j < 4; j++) acc[nt][j] = 0.f;

    const uint32_t* sAr = sA + (wid * 16 + g) * SW + tg;
    const uint2* Bw = (const uint2*)Bfrag + lane;

#pragma unroll
    for (int k16 = 0; k16 < 8; k16++) {
        const int c0 = k16 * 8;
        uint32_t a[4];
        a[0] = sAr[c0];
        a[1] = sAr[8 * SW + c0];
        a[2] = sAr[c0 + 4];
        a[3] = sAr[8 * SW + c0 + 4];
#pragma unroll
        for (int nt = 0; nt < 2; nt++) {
            uint2 t = Bw[(k16 * 2 + nt) * 32];
            uint32_t b[2] = {t.x, t.y};
            mma_f16(acc[nt], a, b);
        }
    }

    const int r0 = m0 + wid * 16 + g;
    const int r1 = r0 + 8;
#pragma unroll
    for (int nt = 0; nt < 2; nt++) {
        int col = nt * 8 + tg * 2;
        float2 bb = *(const float2*)&bo[col];
        if (r0 < NN) {
            out[(size_t)r0 * ODIM + col + 0] = acc[nt][0] + bb.x;
            out[(size_t)r0 * ODIM + col + 1] = acc[nt][1] + bb.y;
        }
        if (r1 < NN) {
            out[(size_t)r1 * ODIM + col + 0] = acc[nt][2] + bb.x;
            out[(size_t)r1 * ODIM + col + 1] = acc[nt][3] + bb.y;
        }
    }
}

// ---------------------------------------------------------------------------
extern "C" void kernel_launch(void* const* d_in, const int* in_sizes, int n_in,
                              void* d_out, int out_size) {
    const float* user = (const float*)d_in[0];
    const float* prod = (const float*)d_in[1];
    const void*  edges = d_in[2];
    const float* Wu = (const float*)d_in[3];
    const float* bu = (const float*)d_in[4];
    const float* Wp = (const float*)d_in[5];
    const float* bp = (const float*)d_in[6];
    const float* W1 = (const float*)d_in[7];
    const float* b1 = (const float*)d_in[8];
    const float* W2 = (const float*)d_in[9];
    const float* b2 = (const float*)d_in[10];
    const float* W3 = (const float*)d_in[11];
    const float* b3 = (const float*)d_in[12];
    const float* Wo = (const float*)d_in[13];
    const float* bo = (const float*)d_in[14];
    float* out = (float*)d_out;

    __half *px = nullptr, *py = nullptr;
    uint32_t* pw = nullptr;
    cudaGetSymbolAddress((void**)&px, g_x);
    cudaGetSymbolAddress((void**)&py, g_y);
    cudaGetSymbolAddress((void**)&pw, g_wfrag);

    // 1: f16 B fragments for all 6 weights (4+7+8+8+8+1 = 36 blocks)
    k_wfrag<<<36, 256>>>(Wu, Wp, W1, W2, W3, Wo);

    // 2-3: input transforms -> g_x (fp16; bias added; no relu: conv1 input)
    k_gemm<4, 36, true, 64><<<(N_USERS + 127) / 128, 256>>>(
        user, N_USERS, pw + OFF_WU, bu, px);
    k_gemm<7, 60, true, 100><<<(N_PRODS + 127) / 128, 256>>>(
        prod, N_PRODS, pw + OFF_WP, bp, px + (size_t)N_USERS * HDIM);

    // 4: layer-1 GEMM (profiled slot #4)
    k_gemm<8, 68, false, 128><<<(NN + 127) / 128, 256>>>(
        px, NN, pw + OFF_W1, nullptr, py);

    // 5-10: CSR build (independent of GEMMs above)
    k_prep<<<(NN + 255) / 256, 256>>>(edges);
    k_hist<<<(NE + 255) / 256, 256>>>(edges);
    k_scan1<<<NBLK1, 256>>>();
    k_scan2<<<1, 128>>>();
    k_scan3<<<(NN + 255) / 256, 256>>>();
    k_fill<<<(NE + 255) / 256, 256>>>(edges);

    // layer 1 gather (+relu)
    k_gather<<<(NN * 32 + 255) / 256, 256>>>(b1);

    // layers 2,3
    k_gemm<8, 68, false, 128><<<(NN + 127) / 128, 256>>>(
        px, NN, pw + OFF_W2, nullptr, py);
    k_gather<<<(NN * 32 + 255) / 256, 256>>>(b2);

    k_gemm<8, 68, false, 128><<<(NN + 127) / 128, 256>>>(
        px, NN, pw + OFF_W3, nullptr, py);
    k_gather<<<(NN * 32 + 255) / 256, 256>>>(b3);

    k_out<<<(NN + 63) / 64, 256>>>(pw + OFF_WO, bo, out);
}

// round 12
// speedup vs baseline: 1.9764x; 1.0199x over previous
#include <cuda_runtime.h>
#include <cuda_fp16.h>
#include <cstdint>
#include <cstddef>

#define N_USERS 50000
#define N_PRODS 50000
#define NN      100000
#define NE      600000
#define HDIM    128
#define ODIM    16
#define NBLK1   98        // ceil(NN/1024)

// Scratch (__device__ globals: allocation-free rule)
__device__ __half   g_x[(size_t)NN * HDIM];
__device__ __half   g_y[(size_t)NN * HDIM];
__device__ float    g_dinv[NN];
__device__ int      g_deg[NN];
__device__ int      g_rowstart[NN + 1];
__device__ int      g_cursor[NN];
__device__ int      g_esrc[NE];
__device__ int      g_blksum[NBLK1];
__device__ int      g_is64;
// f16 B fragments: Wu@0(4096), Wp@4096(7168), W1@11264, W2@19456, W3@27648 (8192 ea), Wo@35840(1024)
__device__ uint32_t g_wfrag[36864];

#define OFF_WU 0
#define OFF_WP 4096
#define OFF_W1 11264
#define OFF_W2 19456
#define OFF_W3 27648
#define OFF_WO 35840

// ---------------------------------------------------------------------------
// helpers (sm_80-class PTX only)
// ---------------------------------------------------------------------------
__device__ __forceinline__ uint32_t packh2(float lo, float hi) {
    __half2 h = __floats2half2_rn(lo, hi);
    return *reinterpret_cast<uint32_t*>(&h);
}
__device__ __forceinline__ void mma_f16(float* c, const uint32_t* a, const uint32_t* b) {
    asm volatile(
        "mma.sync.aligned.m16n8k16.row.col.f32.f16.f16.f32 "
        "{%0,%1,%2,%3}, {%4,%5,%6,%7}, {%8,%9}, {%0,%1,%2,%3};"
        : "+f"(c[0]), "+f"(c[1]), "+f"(c[2]), "+f"(c[3])
        : "r"(a[0]), "r"(a[1]), "r"(a[2]), "r"(a[3]), "r"(b[0]), "r"(b[1]));
}

// ---------------------------------------------------------------------------
// Precompute f16 B fragments for all 6 weights (Wu,Wp,W1,W2,W3 @N=128; Wo @N=16).
// m16n8k16 B tile word w: reg=w&1, lane=w>>1, n'=lane>>2, tg=lane&3;
// word = {B[tg*2+reg*8][n'], B[tg*2+1+reg*8][n']}. Tile (k16,nt) at (k16*NT+nt)*64.
// ---------------------------------------------------------------------------
__global__ __launch_bounds__(256) void k_wfrag(
    const float* __restrict__ Wu, const float* __restrict__ Wp,
    const float* __restrict__ W1, const float* __restrict__ W2,
    const float* __restrict__ W3, const float* __restrict__ Wo)
{
    const int nblk[6] = {4, 7, 8, 8, 8, 1};
    const int offs[6] = {OFF_WU, OFF_WP, OFF_W1, OFF_W2, OFF_W3, OFF_WO};
    const int kds[6]  = {64, 100, 128, 128, 128, 128};
    int b = blockIdx.x, slot = 0;
    while (slot < 6 && b >= nblk[slot]) { b -= nblk[slot]; slot++; }
    if (slot >= 6) return;
    const float* W = (slot == 0) ? Wu : (slot == 1) ? Wp : (slot == 2) ? W1
                   : (slot == 3) ? W2 : (slot == 4) ? W3 : Wo;
    const int Kdim = kds[slot];
    uint32_t* dst = g_wfrag + offs[slot];
    if (slot < 5) {
#pragma unroll
        for (int i = 0; i < 4; i++) {
            int w = b * 1024 + threadIdx.x + i * 256;
            int nt = (w >> 6) & 15;
            int widx = w & 63;
            int reg = widx & 1, lane = widx >> 1;
            int n = nt * 8 + (lane >> 2), tg = lane & 3;
            int k = (w >> 10) * 16 + tg * 2 + reg * 8;
            float lo = (k     < Kdim) ? W[(size_t)k * HDIM + n] : 0.f;
            float hi = (k + 1 < Kdim) ? W[(size_t)(k + 1) * HDIM + n] : 0.f;
            dst[w] = packh2(lo, hi);
        }
    } else {
        // Wo: 128x16, 8 k16 x 2 nt
#pragma unroll
        for (int i = 0; i < 4; i++) {
            int w = threadIdx.x + i * 256;
            int k16 = w >> 7, r = w & 127;
            int nt = (r >> 6) & 1;
            int widx = r & 63;
            int reg = widx & 1, lane = widx >> 1;
            int n = nt * 8 + (lane >> 2), tg = lane & 3;
            int k = k16 * 16 + tg * 2 + reg * 8;
            dst[w] = packh2(W[(size_t)k * ODIM + n], W[(size_t)(k + 1) * ODIM + n]);
        }
    }
}

// ---------------------------------------------------------------------------
// Unified f16 m16n8k16 GEMM: 256 thr, 128x128 CTA tile, warp tile 32x64.
// BOTH operands staged in SMEM: A (row stride SW, SW%8==4 -> conflict-free
// LDS.32) and B fragments (K16*1024 words, coalesced copy; mainloop B reads
// are 64-consecutive-word tiles -> conflict-free LDS.64). All mainloop
// operand latency is ~29cyc LDS instead of ~250cyc L2 -> latency-bound fix.
// F32IN: stage fp32 A (lda=KDIM) packed to f16. else raw fp16 copy (lda=128).
// ---------------------------------------------------------------------------
template<int K16, int SW, bool F32IN, int KDIM>
__global__ __launch_bounds__(256, 2) void k_gemm(
    const void* __restrict__ Av, int M,
    const uint32_t* __restrict__ Bfrag, const float* __restrict__ bias,
    __half* __restrict__ out)
{
    extern __shared__ uint32_t smem[];
    uint32_t* sA = smem;                 // 128 * SW words
    uint32_t* sB = smem + 128 * SW;      // K16 * 1024 words

    const int tid = threadIdx.x;
    const int wid = tid >> 5;
    const int lane = tid & 31;
    const int m0 = blockIdx.x * 128;
    const int wm = wid & 3;
    const int wn = wid >> 2;
    const int g = lane >> 2, tg = lane & 3;

    // ---- stage B fragments: K16*256 uint4, coalesced ----
#pragma unroll
    for (int it = 0; it < K16; it++) {
        int idx = tid + it * 256;
        ((uint4*)sB)[idx] = ((const uint4*)Bfrag)[idx];
    }

    // ---- stage A ----
    if (F32IN) {
        const float* A = (const float*)Av;
        constexpr int KPAD = K16 * 16;
        constexpr int NC4 = KPAD / 4;
#pragma unroll
        for (int it = 0; it < 128 * NC4 / 256; it++) {
            int idx4 = tid + it * 256;
            int r = idx4 / NC4;
            int c4 = (idx4 - r * NC4) * 4;
            int gm = m0 + r;
            float4 v = make_float4(0.f, 0.f, 0.f, 0.f);
            if (gm < M && c4 < KDIM)
                v = *(const float4*)&A[(size_t)gm * KDIM + c4];
            uint32_t* p = sA + r * SW + c4 / 2;
            p[0] = packh2(v.x, v.y);
            p[1] = packh2(v.z, v.w);
        }
    } else {
        const __half* A = (const __half*)Av;
#pragma unroll
        for (int it = 0; it < 8; it++) {
            int idx = tid + it * 256;
            int r = idx >> 4, u = idx & 15;
            int gm = m0 + r;
            uint4 v = make_uint4(0u, 0u, 0u, 0u);
            if (gm < M) v = *(const uint4*)&A[(size_t)gm * HDIM + u * 8];
            *(uint4*)(sA + r * SW + u * 4) = v;
        }
    }
    __syncthreads();

    float acc[2][8][4];
#pragma unroll
    for (int mt = 0; mt < 2; mt++)
#pragma unroll
        for (int nt = 0; nt < 8; nt++)
#pragma unroll
            for (int j = 0; j < 4; j++) acc[mt][nt][j] = 0.f;

    const uint32_t* sAr = sA + (wm * 32 + g) * SW + tg;
    const uint2* Bw = (const uint2*)(sB + (wn * 8) * 64) + lane;

#pragma unroll
    for (int k16 = 0; k16 < K16; k16++) {
        const int c0 = k16 * 8;
        uint32_t a[2][4];
#pragma unroll
        for (int mt = 0; mt < 2; mt++) {
            const uint32_t* p = sAr + mt * 16 * SW;
            a[mt][0] = p[c0];
            a[mt][1] = p[8 * SW + c0];
            a[mt][2] = p[c0 + 4];
            a[mt][3] = p[8 * SW + c0 + 4];
        }
        uint32_t b[8][2];
#pragma unroll
        for (int nt = 0; nt < 8; nt++) {
            uint2 t = Bw[(k16 * 16 + nt) * 32];
            b[nt][0] = t.x; b[nt][1] = t.y;
        }
#pragma unroll
        for (int mt = 0; mt < 2; mt++)
#pragma unroll
            for (int nt = 0; nt < 8; nt++)
                mma_f16(acc[mt][nt], a[mt], b[nt]);
    }

    const int rbase = m0 + wm * 32 + g;
#pragma unroll
    for (int mt = 0; mt < 2; mt++) {
        int r0 = rbase + mt * 16;
        int r1 = r0 + 8;
#pragma unroll
        for (int nt = 0; nt < 8; nt++) {
            int col = wn * 64 + nt * 8 + tg * 2;
            float bx = 0.f, by = 0.f;
            if (bias) {
                float2 bb = *(const float2*)&bias[col];
                bx = bb.x; by = bb.y;
            }
            if (r0 < M)
                *(__half2*)&out[(size_t)r0 * HDIM + col] =
                    __floats2half2_rn(acc[mt][nt][0] + bx, acc[mt][nt][1] + by);
            if (r1 < M)
                *(__half2*)&out[(size_t)r1 * HDIM + col] =
                    __floats2half2_rn(acc[mt][nt][2] + bx, acc[mt][nt][3] + by);
        }
    }
}

// ---------------------------------------------------------------------------
// Edge detect + degree zero (merged) + CSR build
// ---------------------------------------------------------------------------
__global__ void k_prep(const void* __restrict__ edges) {
    int i = blockIdx.x * blockDim.x + threadIdx.x;
    if (i < NN) g_deg[i] = 0;
    if (i == 0) {
        const unsigned int* w = (const unsigned int*)edges;
        int is64 = 1;
        for (int j = 0; j < 64; j++)
            if (w[2 * j + 1] != 0u) { is64 = 0; break; }
        g_is64 = is64;
    }
}
__device__ __forceinline__ void load_edge(const void* edges, int i, int& s, int& d) {
    if (g_is64) {
        const long long* e = (const long long*)edges;
        s = (int)e[i]; d = (int)e[NE + i];
    } else {
        const int* e = (const int*)edges;
        s = e[i]; d = e[NE + i];
    }
}
__global__ void k_hist(const void* __restrict__ edges) {
    int i = blockIdx.x * blockDim.x + threadIdx.x;
    if (i >= NE) return;
    int s, d; load_edge(edges, i, s, d);
    atomicAdd(&g_deg[d], 1);
}
__global__ __launch_bounds__(256) void k_scan1() {
    __shared__ int wsum[8], wbase[8];
    int b = blockIdx.x, tid = threadIdx.x;
    int base = b * 1024 + tid * 4;
    int v0 = 0, v1 = 0, v2 = 0, v3 = 0;
    if (base + 3 < NN) {
        int4 t = *(const int4*)&g_deg[base];
        v0 = t.x; v1 = t.y; v2 = t.z; v3 = t.w;
    } else {
        if (base + 0 < NN) v0 = g_deg[base + 0];
        if (base + 1 < NN) v1 = g_deg[base + 1];
        if (base + 2 < NN) v2 = g_deg[base + 2];
        if (base + 3 < NN) v3 = g_deg[base + 3];
    }
    int s = v0 + v1 + v2 + v3;
    int lane = tid & 31, w = tid >> 5;
    int x = s;
#pragma unroll
    for (int off = 1; off < 32; off <<= 1) {
        int t = __shfl_up_sync(0xffffffffu, x, off);
        if (lane >= off) x += t;
    }
    if (lane == 31) wsum[w] = x;
    __syncthreads();
    if (tid == 0) {
        int run = 0;
#pragma unroll
        for (int i = 0; i < 8; i++) { wbase[i] = run; run += wsum[i]; }
        g_blksum[b] = run;
    }
    __syncthreads();
    int ex = wbase[w] + x - s;
    if (base + 0 < NN) g_rowstart[base + 0] = ex;
    if (base + 1 < NN) g_rowstart[base + 1] = ex + v0;
    if (base + 2 < NN) g_rowstart[base + 2] = ex + v0 + v1;
    if (base + 3 < NN) g_rowstart[base + 3] = ex + v0 + v1 + v2;
}
__global__ __launch_bounds__(128) void k_scan2() {
    __shared__ int sh[NBLK1];
    int tid = threadIdx.x;
    if (tid < NBLK1) sh[tid] = g_blksum[tid];
    __syncthreads();
    if (tid == 0) {
        int run = 0;
        for (int i = 0; i < NBLK1; i++) { int t = sh[i]; sh[i] = run; run += t; }
    }
    __syncthreads();
    if (tid < NBLK1) g_blksum[tid] = sh[tid];
}
__global__ void k_scan3() {
    int i = blockIdx.x * blockDim.x + threadIdx.x;
    if (i >= NN) return;
    int rs = g_rowstart[i] + g_blksum[i >> 10];
    g_rowstart[i] = rs;
    g_cursor[i] = rs;
    g_dinv[i] = rsqrtf((float)g_deg[i] + 1.0f);
    if (i == 0) g_rowstart[NN] = NE;
}
__global__ void k_fill(const void* __restrict__ edges) {
    int i = blockIdx.x * blockDim.x + threadIdx.x;
    if (i >= NE) return;
    int s, d; load_edge(edges, i, s, d);
    int pos = atomicAdd(&g_cursor[d], 1);
    g_esrc[pos] = s;
}

// ---------------------------------------------------------------------------
// CSR gather + fused ReLU, fp16 in/out. Lane covers cols lane*4..lane*4+3.
// ---------------------------------------------------------------------------
__device__ __forceinline__ void h4_to_f4(uint2 t, float4& f) {
    float2 a = __half22float2(*reinterpret_cast<__half2*>(&t.x));
    float2 b = __half22float2(*reinterpret_cast<__half2*>(&t.y));
    f.x = a.x; f.y = a.y; f.z = b.x; f.w = b.y;
}
__global__ __launch_bounds__(256) void k_gather(const float* __restrict__ bias) {
    int gt = blockIdx.x * blockDim.x + threadIdx.x;
    int node = gt >> 5;
    int lane = gt & 31;
    if (node >= NN) return;

    const int co = lane * 4;
    float dd = g_dinv[node];
    float4 acc;
    {
        uint2 t = *(const uint2*)&g_y[(size_t)node * HDIM + co];
        h4_to_f4(t, acc);
        acc.x *= dd; acc.y *= dd; acc.z *= dd; acc.w *= dd;
    }

    int e = g_rowstart[node];
    const int end = g_rowstart[node + 1];
    for (; e + 4 <= end; e += 4) {
        int s0 = g_esrc[e], s1 = g_esrc[e + 1], s2 = g_esrc[e + 2], s3 = g_esrc[e + 3];
        float n0 = g_dinv[s0], n1 = g_dinv[s1], n2 = g_dinv[s2], n3 = g_dinv[s3];
        uint2 t0 = *(const uint2*)&g_y[(size_t)s0 * HDIM + co];
        uint2 t1 = *(const uint2*)&g_y[(size_t)s1 * HDIM + co];
        uint2 t2 = *(const uint2*)&g_y[(size_t)s2 * HDIM + co];
        uint2 t3 = *(const uint2*)&g_y[(size_t)s3 * HDIM + co];
        float4 a, b, c, d;
        h4_to_f4(t0, a); h4_to_f4(t1, b); h4_to_f4(t2, c); h4_to_f4(t3, d);
        acc.x += a.x * n0 + b.x * n1 + c.x * n2 + d.x * n3;
        acc.y += a.y * n0 + b.y * n1 + c.y * n2 + d.y * n3;
        acc.z += a.z * n0 + b.z * n1 + c.z * n2 + d.z * n3;
        acc.w += a.w * n0 + b.w * n1 + c.w * n2 + d.w * n3;
    }
    for (; e < end; e++) {
        int s = g_esrc[e];
        float ns = g_dinv[s];
        uint2 t = *(const uint2*)&g_y[(size_t)s * HDIM + co];
        float4 a; h4_to_f4(t, a);
        acc.x += a.x * ns; acc.y += a.y * ns; acc.z += a.z * ns; acc.w += a.w * ns;
    }
    float4 bb = *(const float4*)&bias[co];
    float ox = fmaxf(acc.x * dd + bb.x, 0.f);
    float oy = fmaxf(acc.y * dd + bb.y, 0.f);
    float oz = fmaxf(acc.z * dd + bb.z, 0.f);
    float ow = fmaxf(acc.w * dd + bb.w, 0.f);
    uint2 o;
    *reinterpret_cast<__half2*>(&o.x) = __floats2half2_rn(ox, oy);
    *reinterpret_cast<__half2*>(&o.y) = __floats2half2_rn(oz, ow);
    *(uint2*)&g_x[(size_t)node * HDIM + co] = o;
}

// ---------------------------------------------------------------------------
// Output GEMM (f16 mma): out[NN,16] = g_x @ Wo + bo.
// CTA 128 rows, 8 warps, warp tile 16x16. Wo fragments staged in SMEM too.
// ---------------------------------------------------------------------------
__global__ __launch_bounds__(256) void k_out(
    const uint32_t* __restrict__ Bfrag, const float* __restrict__ bo,
    float* __restrict__ out)
{
    constexpr int SW = 68;
    __shared__ uint32_t sA[128 * SW];
    __shared__ uint32_t sB[1024];
    const int tid = threadIdx.x;
    const int wid = tid >> 5;
    const int lane = tid & 31;
    const int m0 = blockIdx.x * 128;
    const int g = lane >> 2, tg = lane & 3;

    ((uint4*)sB)[tid] = ((const uint4*)Bfrag)[tid];
#pragma unroll
    for (int it = 0; it < 8; it++) {
        int idx = tid + it * 256;
        int r = idx >> 4, u = idx & 15;
        int gm = m0 + r;
        uint4 v = make_uint4(0u, 0u, 0u, 0u);
        if (gm < NN) v = *(const uint4*)&g_x[(size_t)gm * HDIM + u * 8];
        *(uint4*)(sA + r * SW + u * 4) = v;
    }
    __syncthreads();

    float acc[2][4];
#pragma unroll
    for (int nt = 0; nt < 2; nt++)
#pragma unroll
        for (int j = 0; j < 4; j++) acc[nt][j] = 0.f;

    const uint32_t* sAr = sA + (wid * 16 + g) * SW + tg;
    const uint2* Bw = (const uint2*)sB + lane;

#pragma unroll
    for (int k16 = 0; k16 < 8; k16++) {
        const int c0 = k16 * 8;
        uint32_t a[4];
        a[0] = sAr[c0];
        a[1] = sAr[8 * SW + c0];
        a[2] = sAr[c0 + 4];
        a[3] = sAr[8 * SW + c0 + 4];
#pragma unroll
        for (int nt = 0; nt < 2; nt++) {
            uint2 t = Bw[(k16 * 2 + nt) * 32];
            uint32_t b[2] = {t.x, t.y};
            mma_f16(acc[nt], a, b);
        }
    }

    const int r0 = m0 + wid * 16 + g;
    const int r1 = r0 + 8;
#pragma unroll
    for (int nt = 0; nt < 2; nt++) {
        int col = nt * 8 + tg * 2;
        float2 bb = *(const float2*)&bo[col];
        if (r0 < NN) {
            out[(size_t)r0 * ODIM + col + 0] = acc[nt][0] + bb.x;
            out[(size_t)r0 * ODIM + col + 1] = acc[nt][1] + bb.y;
        }
        if (r1 < NN) {
            out[(size_t)r1 * ODIM + col + 0] = acc[nt][2] + bb.x;
            out[(size_t)r1 * ODIM + col + 1] = acc[nt][3] + bb.y;
        }
    }
}

// ---------------------------------------------------------------------------
extern "C" void kernel_launch(void* const* d_in, const int* in_sizes, int n_in,
                              void* d_out, int out_size) {
    const float* user = (const float*)d_in[0];
    const float* prod = (const float*)d_in[1];
    const void*  edges = d_in[2];
    const float* Wu = (const float*)d_in[3];
    const float* bu = (const float*)d_in[4];
    const float* Wp = (const float*)d_in[5];
    const float* bp = (const float*)d_in[6];
    const float* W1 = (const float*)d_in[7];
    const float* b1 = (const float*)d_in[8];
    const float* W2 = (const float*)d_in[9];
    const float* b2 = (const float*)d_in[10];
    const float* W3 = (const float*)d_in[11];
    const float* b3 = (const float*)d_in[12];
    const float* Wo = (const float*)d_in[13];
    const float* bo = (const float*)d_in[14];
    float* out = (float*)d_out;

    __half *px = nullptr, *py = nullptr;
    uint32_t* pw = nullptr;
    cudaGetSymbolAddress((void**)&px, g_x);
    cudaGetSymbolAddress((void**)&py, g_y);
    cudaGetSymbolAddress((void**)&pw, g_wfrag);

    const int smemU = (128 * 36 + 4 * 1024) * 4;   // 34816
    const int smemP = (128 * 60 + 7 * 1024) * 4;   // 59392
    const int smemL = (128 * 68 + 8 * 1024) * 4;   // 67584
    cudaFuncSetAttribute(k_gemm<4, 36, true, 64>,
        cudaFuncAttributeMaxDynamicSharedMemorySize, smemU);
    cudaFuncSetAttribute(k_gemm<7, 60, true, 100>,
        cudaFuncAttributeMaxDynamicSharedMemorySize, smemP);
    cudaFuncSetAttribute(k_gemm<8, 68, false, 128>,
        cudaFuncAttributeMaxDynamicSharedMemorySize, smemL);

    // 1: f16 B fragments for all 6 weights (4+7+8+8+8+1 = 36 blocks)
    k_wfrag<<<36, 256>>>(Wu, Wp, W1, W2, W3, Wo);

    // 2-3: input transforms -> g_x (fp16; bias added; no relu: conv1 input)
    k_gemm<4, 36, true, 64><<<(N_USERS + 127) / 128, 256, smemU>>>(
        user, N_USERS, pw + OFF_WU, bu, px);
    k_gemm<7, 60, true, 100><<<(N_PRODS + 127) / 128, 256, smemP>>>(
        prod, N_PRODS, pw + OFF_WP, bp, px + (size_t)N_USERS * HDIM);

    // 4: layer-1 GEMM (profiled slot #4)
    k_gemm<8, 68, false, 128><<<(NN + 127) / 128, 256, smemL>>>(
        px, NN, pw + OFF_W1, nullptr, py);

    // 5-10: CSR build (independent of GEMMs above)
    k_prep<<<(NN + 255) / 256, 256>>>(edges);
    k_hist<<<(NE + 255) / 256, 256>>>(edges);
    k_scan1<<<NBLK1, 256>>>();
    k_scan2<<<1, 128>>>();
    k_scan3<<<(NN + 255) / 256, 256>>>();
    k_fill<<<(NE + 255) / 256, 256>>>(edges);

    // layer 1 gather (+relu)
    k_gather<<<(NN * 32 + 255) / 256, 256>>>(b1);

    // layers 2,3
    k_gemm<8, 68, false, 128><<<(NN + 127) / 128, 256, smemL>>>(
        px, NN, pw + OFF_W2, nullptr, py);
    k_gather<<<(NN * 32 + 255) / 256, 256>>>(b2);

    k_gemm<8, 68, false, 128><<<(NN + 127) / 128, 256, smemL>>>(
        px, NN, pw + OFF_W3, nullptr, py);
    k_gather<<<(NN * 32 + 255) / 256, 256>>>(b3);

    k_out<<<(NN + 63) / 64, 256>>>(pw + OFF_WO, bo, out);
}